// round 1
// baseline (speedup 1.0000x reference)
#include <cuda_runtime.h>
#include <math.h>

// Problem dims (fixed)
#define B_  8
#define N_  1024
#define D_  1024
#define H_  16
#define HD_ 64
#define M_  (B_ * N_)      // 8192 rows
#define N3_ (3 * D_)       // 3072

// ---------------- scratch (device globals; no allocation allowed) ----------
__device__ float g_qkv[(size_t)M_ * N3_];          // 96 MB
__device__ float g_q  [(size_t)B_ * H_ * N_ * HD_]; // 33.5 MB, [b,h,n,d]
__device__ float g_k  [(size_t)B_ * H_ * N_ * HD_];
__device__ float g_v  [(size_t)B_ * H_ * N_ * HD_];
__device__ float g_o  [(size_t)M_ * D_];            // 32 MB, [b*n, h*hd+d]
__device__ float g_cos[N_ * 32];
__device__ float g_sin[N_ * 32];

// ---------------- RoPE tables ---------------------------------------------
__global__ void rope_tables_kernel() {
    int i = blockIdx.x * blockDim.x + threadIdx.x;
    if (i >= N_ * 32) return;
    int n = i >> 5, j = i & 31;
    int pos = (j < 16) ? (n >> 5) : (n & 31);   // row idx or col idx (side=32)
    int jj  = (j < 16) ? j : (j - 16);
    double invf = pow(10000.0, -(double)jj / 16.0);
    double ang  = (double)pos * invf;
    g_cos[i] = (float)cos(ang);
    g_sin[i] = (float)sin(ang);
}

// ---------------- tiled SGEMM with bias: C = A@B + bias --------------------
#define BM 128
#define BN 128
#define BK 16
#define TM 8
#define TN 8

__global__ __launch_bounds__(256)
void sgemm_bias_kernel(const float* __restrict__ A, const float* __restrict__ Bm,
                       const float* __restrict__ bias, float* __restrict__ C,
                       int M, int N, int K)
{
    __shared__ float As[BK][BM];
    __shared__ float Bs[BK][BN];
    const int tid  = threadIdx.x;
    const int brow = blockIdx.y * BM;
    const int bcol = blockIdx.x * BN;
    const int tr   = (tid / 16) * TM;
    const int tc   = (tid % 16) * TN;

    float acc[TM][TN];
    #pragma unroll
    for (int i = 0; i < TM; i++)
        #pragma unroll
        for (int j = 0; j < TN; j++) acc[i][j] = 0.f;

    const int arow0 = tid >> 2;        // 0..63
    const int acol0 = (tid & 3) * 4;   // 0,4,8,12
    const int brow0 = tid >> 5;        // 0..7
    const int bcol0 = (tid & 31) * 4;  // 0..124

    for (int k0 = 0; k0 < K; k0 += BK) {
        #pragma unroll
        for (int i = 0; i < 2; i++) {
            int r = arow0 + i * 64;
            float4 v = *(const float4*)&A[(size_t)(brow + r) * K + k0 + acol0];
            As[acol0 + 0][r] = v.x;
            As[acol0 + 1][r] = v.y;
            As[acol0 + 2][r] = v.z;
            As[acol0 + 3][r] = v.w;
        }
        #pragma unroll
        for (int i = 0; i < 2; i++) {
            int r = brow0 + i * 8;
            *(float4*)&Bs[r][bcol0] =
                *(const float4*)&Bm[(size_t)(k0 + r) * N + bcol + bcol0];
        }
        __syncthreads();

        #pragma unroll
        for (int kk = 0; kk < BK; kk++) {
            float ra[TM], rb[TN];
            #pragma unroll
            for (int i = 0; i < TM; i++) ra[i] = As[kk][tr + i];
            #pragma unroll
            for (int j = 0; j < TN; j++) rb[j] = Bs[kk][tc + j];
            #pragma unroll
            for (int i = 0; i < TM; i++)
                #pragma unroll
                for (int j = 0; j < TN; j++)
                    acc[i][j] = fmaf(ra[i], rb[j], acc[i][j]);
        }
        __syncthreads();
    }

    #pragma unroll
    for (int i = 0; i < TM; i++) {
        #pragma unroll
        for (int j = 0; j < TN; j += 4) {
            float4 v;
            v.x = acc[i][j + 0] + bias[bcol + tc + j + 0];
            v.y = acc[i][j + 1] + bias[bcol + tc + j + 1];
            v.z = acc[i][j + 2] + bias[bcol + tc + j + 2];
            v.w = acc[i][j + 3] + bias[bcol + tc + j + 3];
            *(float4*)&C[(size_t)(brow + tr + i) * N + bcol + tc + j] = v;
        }
    }
}

// ---------------- fused RMSNorm + RoPE + reshape to [b,h,n,d] --------------
__global__ __launch_bounds__(256)
void rmsnorm_rope_kernel(const float* __restrict__ q_scale,
                         const float* __restrict__ k_scale)
{
    int gw   = (blockIdx.x * blockDim.x + threadIdx.x) >> 5;  // one warp per (b,n,h)
    int lane = threadIdx.x & 31;
    int h  = gw & 15;
    int bn = gw >> 4;              // b*1024 + n
    int n  = bn & (N_ - 1);
    const float* src = g_qkv + (size_t)bn * N3_;
    float cs = g_cos[n * 32 + lane];
    float sn = g_sin[n * 32 + lane];
    int bh = (bn >> 10) * H_ + h;
    size_t dst = ((size_t)bh * N_ + n) * HD_;

    // Q: rmsnorm + rope
    {
        float t1 = src[h * HD_ + lane];
        float t2 = src[h * HD_ + lane + 32];
        float ss = t1 * t1 + t2 * t2;
        #pragma unroll
        for (int o = 16; o > 0; o >>= 1) ss += __shfl_xor_sync(0xffffffffu, ss, o);
        float rs = rsqrtf(ss * (1.0f / HD_) + 1e-6f);
        t1 *= rs * q_scale[lane];
        t2 *= rs * q_scale[lane + 32];
        g_q[dst + lane]      = t1 * cs - t2 * sn;
        g_q[dst + lane + 32] = t1 * sn + t2 * cs;
    }
    // K: rmsnorm + rope
    {
        float t1 = src[D_ + h * HD_ + lane];
        float t2 = src[D_ + h * HD_ + lane + 32];
        float ss = t1 * t1 + t2 * t2;
        #pragma unroll
        for (int o = 16; o > 0; o >>= 1) ss += __shfl_xor_sync(0xffffffffu, ss, o);
        float rs = rsqrtf(ss * (1.0f / HD_) + 1e-6f);
        t1 *= rs * k_scale[lane];
        t2 *= rs * k_scale[lane + 32];
        g_k[dst + lane]      = t1 * cs - t2 * sn;
        g_k[dst + lane + 32] = t1 * sn + t2 * cs;
    }
    // V: copy/reshape
    g_v[dst + lane]      = src[2 * D_ + h * HD_ + lane];
    g_v[dst + lane + 32] = src[2 * D_ + h * HD_ + lane + 32];
}

// ---------------- flash attention (fp32) -----------------------------------
// One thread = one query row. Block = 128 threads. Grid = (N/128, B*H).
__global__ __launch_bounds__(128)
void attn_kernel()
{
    const int bh = blockIdx.y;
    const int qi = blockIdx.x * 128 + threadIdx.x;
    const size_t base = (size_t)bh * N_ * HD_;
    const float scale = 0.125f;  // 1/sqrt(64)

    float q[HD_];
    #pragma unroll
    for (int d4 = 0; d4 < 16; d4++) {
        float4 v = *(const float4*)&g_q[base + (size_t)qi * HD_ + d4 * 4];
        q[d4 * 4 + 0] = v.x * scale;
        q[d4 * 4 + 1] = v.y * scale;
        q[d4 * 4 + 2] = v.z * scale;
        q[d4 * 4 + 3] = v.w * scale;
    }
    float o[HD_];
    #pragma unroll
    for (int d = 0; d < HD_; d++) o[d] = 0.f;
    float m = -3.0e38f, l = 0.f;

    __shared__ float ks[64 * HD_];
    __shared__ float vs[64 * HD_];

    for (int t = 0; t < N_ / 64; t++) {
        __syncthreads();
        const float4* kg = (const float4*)(g_k + base + (size_t)t * 64 * HD_);
        const float4* vg = (const float4*)(g_v + base + (size_t)t * 64 * HD_);
        #pragma unroll
        for (int i = 0; i < 8; i++) {
            int idx = threadIdx.x + i * 128;
            ((float4*)ks)[idx] = kg[idx];
            ((float4*)vs)[idx] = vg[idx];
        }
        __syncthreads();

        for (int j = 0; j < 64; j++) {
            float s = 0.f;
            const float4* kr = (const float4*)&ks[j * HD_];
            #pragma unroll
            for (int d4 = 0; d4 < 16; d4++) {
                float4 kv = kr[d4];
                s = fmaf(q[d4 * 4 + 0], kv.x, s);
                s = fmaf(q[d4 * 4 + 1], kv.y, s);
                s = fmaf(q[d4 * 4 + 2], kv.z, s);
                s = fmaf(q[d4 * 4 + 3], kv.w, s);
            }
            float mn = fmaxf(m, s);
            if (mn > m) {
                float corr = __expf(m - mn);
                l *= corr;
                #pragma unroll
                for (int d = 0; d < HD_; d++) o[d] *= corr;
                m = mn;
            }
            float p = __expf(s - m);
            l += p;
            const float4* vr = (const float4*)&vs[j * HD_];
            #pragma unroll
            for (int d4 = 0; d4 < 16; d4++) {
                float4 vv = vr[d4];
                o[d4 * 4 + 0] = fmaf(p, vv.x, o[d4 * 4 + 0]);
                o[d4 * 4 + 1] = fmaf(p, vv.y, o[d4 * 4 + 1]);
                o[d4 * 4 + 2] = fmaf(p, vv.z, o[d4 * 4 + 2]);
                o[d4 * 4 + 3] = fmaf(p, vv.w, o[d4 * 4 + 3]);
            }
        }
    }

    float inv = 1.0f / l;
    // write to [b*n, h*64+d] layout for the output GEMM
    size_t orow = ((size_t)(bh >> 4) * N_ + qi) * D_ + (size_t)(bh & 15) * HD_;
    #pragma unroll
    for (int d4 = 0; d4 < 16; d4++) {
        float4 v;
        v.x = o[d4 * 4 + 0] * inv;
        v.y = o[d4 * 4 + 1] * inv;
        v.z = o[d4 * 4 + 2] * inv;
        v.w = o[d4 * 4 + 3] * inv;
        *(float4*)&g_o[orow + d4 * 4] = v;
    }
}

// ---------------- launch ----------------------------------------------------
extern "C" void kernel_launch(void* const* d_in, const int* in_sizes, int n_in,
                              void* d_out, int out_size)
{
    const float* x       = (const float*)d_in[0];
    const float* Wqkv    = (const float*)d_in[1];
    const float* bqkv    = (const float*)d_in[2];
    const float* Wout    = (const float*)d_in[3];
    const float* bout    = (const float*)d_in[4];
    const float* q_scale = (const float*)d_in[5];
    const float* k_scale = (const float*)d_in[6];
    float* out = (float*)d_out;

    float *qkv_p = nullptr, *o_p = nullptr;
    cudaGetSymbolAddress((void**)&qkv_p, g_qkv);
    cudaGetSymbolAddress((void**)&o_p,   g_o);

    // 1. RoPE cos/sin tables
    rope_tables_kernel<<<(N_ * 32 + 255) / 256, 256>>>();

    // 2. QKV GEMM: [8192,1024] @ [1024,3072] + bias
    dim3 g1(N3_ / BN, M_ / BM);
    sgemm_bias_kernel<<<g1, 256>>>(x, Wqkv, bqkv, qkv_p, M_, N3_, D_);

    // 3. RMSNorm + RoPE + reshape
    rmsnorm_rope_kernel<<<(B_ * N_ * H_) / 8, 256>>>(q_scale, k_scale);

    // 4. Flash attention
    attn_kernel<<<dim3(N_ / 128, B_ * H_), 128>>>();

    // 5. Output GEMM: [8192,1024] @ [1024,1024] + bias
    dim3 g2(D_ / BN, M_ / BM);
    sgemm_bias_kernel<<<g2, 256>>>(o_p, Wout, bout, out, M_, D_, D_);
}

// round 2
// speedup vs baseline: 1.5254x; 1.5254x over previous
#include <cuda_runtime.h>
#include <math.h>

// Problem dims (fixed)
#define B_  8
#define N_  1024
#define D_  1024
#define H_  16
#define HD_ 64
#define M_  (B_ * N_)      // 8192 rows
#define N3_ (3 * D_)       // 3072

// ---------------- scratch (device globals; no allocation allowed) ----------
__device__ float g_qkv[(size_t)M_ * N3_];          // 96 MB
__device__ float g_q  [(size_t)B_ * H_ * N_ * HD_]; // 33.5 MB, [b,h,n,d]
__device__ float g_k  [(size_t)B_ * H_ * N_ * HD_];
__device__ float g_v  [(size_t)B_ * H_ * N_ * HD_];
__device__ float g_o  [(size_t)M_ * D_];            // 32 MB, [b*n, h*hd+d]
__device__ float g_cos[N_ * 32];
__device__ float g_sin[N_ * 32];

// ---------------- RoPE tables ---------------------------------------------
__global__ void rope_tables_kernel() {
    int i = blockIdx.x * blockDim.x + threadIdx.x;
    if (i >= N_ * 32) return;
    int n = i >> 5, j = i & 31;
    int pos = (j < 16) ? (n >> 5) : (n & 31);   // row idx or col idx (side=32)
    int jj  = (j < 16) ? j : (j - 16);
    double invf = pow(10000.0, -(double)jj / 16.0);
    double ang  = (double)pos * invf;
    g_cos[i] = (float)cos(ang);
    g_sin[i] = (float)sin(ang);
}

// ====================== tf32 tensor-core GEMM + bias ========================
// C[M,N] = A[M,K] @ B[K,N] + bias, via mma.sync.m16n8k8 tf32.
// Block tile 128x256x16, 8 warps (2x4), warp tile 64x64.
#define GBM 128
#define GBN 256
#define GBK 16
#define ASTRIDE 20          // A smem row stride (floats), conflict-free frag LDS
#define BSTRIDE 260         // B smem row stride
#define A_ELEMS (GBM * ASTRIDE)   // 2560
#define B_ELEMS (GBK * BSTRIDE)   // 4160
#define GEMM_SMEM_BYTES ((2 * A_ELEMS + 2 * B_ELEMS) * 4)  // 53760

__device__ __forceinline__ unsigned f2tf32(float f) {
    unsigned u;
    asm("cvt.rna.tf32.f32 %0, %1;" : "=r"(u) : "f"(f));
    return u;
}

__global__ __launch_bounds__(256, 1)
void gemm_tf32_bias(const float* __restrict__ A, const float* __restrict__ Bm,
                    const float* __restrict__ bias, float* __restrict__ C,
                    int M, int N, int K)
{
    extern __shared__ unsigned sm[];
    unsigned* As = sm;                       // [2][GBM][ASTRIDE]
    unsigned* Bs = sm + 2 * A_ELEMS;         // [2][GBK][BSTRIDE]

    const int tid  = threadIdx.x;
    const int warp = tid >> 5;
    const int lane = tid & 31;
    const int wm   = warp & 1;               // 0..1 (M)
    const int wn   = warp >> 1;              // 0..3 (N)
    const int g    = lane >> 2;              // group id 0..7
    const int t    = lane & 3;               // thread-in-group 0..3
    const int brow = blockIdx.y * GBM;
    const int bcol = blockIdx.x * GBN;

    // global-load index mapping (fixed per thread)
    const int ar0 = tid >> 2;                // A rows: idx>>2
    const int akc = (tid & 3) << 2;          // A k-offset (float4)
    const int bnc = (tid & 63) << 2;         // B col offset (float4)
    const int bkr = tid >> 6;                // B k row base

    float acc[4][8][4];
    #pragma unroll
    for (int i = 0; i < 4; i++)
        #pragma unroll
        for (int j = 0; j < 8; j++)
            #pragma unroll
            for (int c = 0; c < 4; c++) acc[i][j][c] = 0.f;

    float4 la[2], lb[4];

    // prologue: load k0=0
    #pragma unroll
    for (int it = 0; it < 2; it++)
        la[it] = *(const float4*)&A[(size_t)(brow + ar0 + it * 64) * K + akc];
    #pragma unroll
    for (int it = 0; it < 4; it++)
        lb[it] = *(const float4*)&Bm[(size_t)(bkr + it * 4) * N + bcol + bnc];

    {   // store buffer 0
        unsigned* Ab = As;
        unsigned* Bb = Bs;
        #pragma unroll
        for (int it = 0; it < 2; it++) {
            uint4 v = { f2tf32(la[it].x), f2tf32(la[it].y), f2tf32(la[it].z), f2tf32(la[it].w) };
            *(uint4*)&Ab[(ar0 + it * 64) * ASTRIDE + akc] = v;
        }
        #pragma unroll
        for (int it = 0; it < 4; it++) {
            uint4 v = { f2tf32(lb[it].x), f2tf32(lb[it].y), f2tf32(lb[it].z), f2tf32(lb[it].w) };
            *(uint4*)&Bb[(bkr + it * 4) * BSTRIDE + bnc] = v;
        }
    }
    __syncthreads();

    const int T = K / GBK;
    for (int ti = 0; ti < T; ti++) {
        // prefetch next tile into registers
        if (ti + 1 < T) {
            int k0 = (ti + 1) * GBK;
            #pragma unroll
            for (int it = 0; it < 2; it++)
                la[it] = *(const float4*)&A[(size_t)(brow + ar0 + it * 64) * K + k0 + akc];
            #pragma unroll
            for (int it = 0; it < 4; it++)
                lb[it] = *(const float4*)&Bm[(size_t)(k0 + bkr + it * 4) * N + bcol + bnc];
        }

        // compute on current buffer
        {
            const unsigned* Ab = As + (ti & 1) * A_ELEMS;
            const unsigned* Bb = Bs + (ti & 1) * B_ELEMS;
            #pragma unroll
            for (int ks = 0; ks < 2; ks++) {
                const int kb = ks * 8;
                unsigned af[4][4], bf[8][2];
                #pragma unroll
                for (int i = 0; i < 4; i++) {
                    int m0 = wm * 64 + i * 16 + g;
                    af[i][0] = Ab[(m0    ) * ASTRIDE + kb + t    ];
                    af[i][1] = Ab[(m0 + 8) * ASTRIDE + kb + t    ];
                    af[i][2] = Ab[(m0    ) * ASTRIDE + kb + t + 4];
                    af[i][3] = Ab[(m0 + 8) * ASTRIDE + kb + t + 4];
                }
                #pragma unroll
                for (int j = 0; j < 8; j++) {
                    int n0 = wn * 64 + j * 8 + g;
                    bf[j][0] = Bb[(kb + t    ) * BSTRIDE + n0];
                    bf[j][1] = Bb[(kb + t + 4) * BSTRIDE + n0];
                }
                #pragma unroll
                for (int i = 0; i < 4; i++)
                    #pragma unroll
                    for (int j = 0; j < 8; j++) {
                        asm volatile(
                            "mma.sync.aligned.m16n8k8.row.col.f32.tf32.tf32.f32 "
                            "{%0,%1,%2,%3},{%4,%5,%6,%7},{%8,%9},{%0,%1,%2,%3};\n"
                            : "+f"(acc[i][j][0]), "+f"(acc[i][j][1]),
                              "+f"(acc[i][j][2]), "+f"(acc[i][j][3])
                            : "r"(af[i][0]), "r"(af[i][1]), "r"(af[i][2]), "r"(af[i][3]),
                              "r"(bf[j][0]), "r"(bf[j][1]));
                    }
            }
        }

        // store prefetched tile into alternate buffer
        if (ti + 1 < T) {
            unsigned* Ab = As + ((ti + 1) & 1) * A_ELEMS;
            unsigned* Bb = Bs + ((ti + 1) & 1) * B_ELEMS;
            #pragma unroll
            for (int it = 0; it < 2; it++) {
                uint4 v = { f2tf32(la[it].x), f2tf32(la[it].y), f2tf32(la[it].z), f2tf32(la[it].w) };
                *(uint4*)&Ab[(ar0 + it * 64) * ASTRIDE + akc] = v;
            }
            #pragma unroll
            for (int it = 0; it < 4; it++) {
                uint4 v = { f2tf32(lb[it].x), f2tf32(lb[it].y), f2tf32(lb[it].z), f2tf32(lb[it].w) };
                *(uint4*)&Bb[(bkr + it * 4) * BSTRIDE + bnc] = v;
            }
        }
        __syncthreads();
    }

    // epilogue: bias + store
    #pragma unroll
    for (int i = 0; i < 4; i++) {
        int row = brow + wm * 64 + i * 16 + g;
        #pragma unroll
        for (int j = 0; j < 8; j++) {
            int col = bcol + wn * 64 + j * 8 + t * 2;
            float b0 = bias[col], b1 = bias[col + 1];
            float2 v0 = { acc[i][j][0] + b0, acc[i][j][1] + b1 };
            float2 v1 = { acc[i][j][2] + b0, acc[i][j][3] + b1 };
            *(float2*)&C[(size_t)row * N + col]       = v0;
            *(float2*)&C[(size_t)(row + 8) * N + col] = v1;
        }
    }
}

// ---------------- fused RMSNorm + RoPE + reshape to [b,h,n,d] --------------
__global__ __launch_bounds__(256)
void rmsnorm_rope_kernel(const float* __restrict__ q_scale,
                         const float* __restrict__ k_scale)
{
    int gw   = (blockIdx.x * blockDim.x + threadIdx.x) >> 5;  // one warp per (b,n,h)
    int lane = threadIdx.x & 31;
    int h  = gw & 15;
    int bn = gw >> 4;              // b*1024 + n
    int n  = bn & (N_ - 1);
    const float* src = g_qkv + (size_t)bn * N3_;
    float cs = g_cos[n * 32 + lane];
    float sn = g_sin[n * 32 + lane];
    int bh = (bn >> 10) * H_ + h;
    size_t dst = ((size_t)bh * N_ + n) * HD_;

    // Q: rmsnorm + rope
    {
        float t1 = src[h * HD_ + lane];
        float t2 = src[h * HD_ + lane + 32];
        float ss = t1 * t1 + t2 * t2;
        #pragma unroll
        for (int o = 16; o > 0; o >>= 1) ss += __shfl_xor_sync(0xffffffffu, ss, o);
        float rs = rsqrtf(ss * (1.0f / HD_) + 1e-6f);
        t1 *= rs * q_scale[lane];
        t2 *= rs * q_scale[lane + 32];
        g_q[dst + lane]      = t1 * cs - t2 * sn;
        g_q[dst + lane + 32] = t1 * sn + t2 * cs;
    }
    // K: rmsnorm + rope
    {
        float t1 = src[D_ + h * HD_ + lane];
        float t2 = src[D_ + h * HD_ + lane + 32];
        float ss = t1 * t1 + t2 * t2;
        #pragma unroll
        for (int o = 16; o > 0; o >>= 1) ss += __shfl_xor_sync(0xffffffffu, ss, o);
        float rs = rsqrtf(ss * (1.0f / HD_) + 1e-6f);
        t1 *= rs * k_scale[lane];
        t2 *= rs * k_scale[lane + 32];
        g_k[dst + lane]      = t1 * cs - t2 * sn;
        g_k[dst + lane + 32] = t1 * sn + t2 * cs;
    }
    // V: copy/reshape
    g_v[dst + lane]      = src[2 * D_ + h * HD_ + lane];
    g_v[dst + lane + 32] = src[2 * D_ + h * HD_ + lane + 32];
}

// ---------------- flash attention (fp32) -----------------------------------
__global__ __launch_bounds__(128)
void attn_kernel()
{
    const int bh = blockIdx.y;
    const int qi = blockIdx.x * 128 + threadIdx.x;
    const size_t base = (size_t)bh * N_ * HD_;
    const float scale = 0.125f;  // 1/sqrt(64)

    float q[HD_];
    #pragma unroll
    for (int d4 = 0; d4 < 16; d4++) {
        float4 v = *(const float4*)&g_q[base + (size_t)qi * HD_ + d4 * 4];
        q[d4 * 4 + 0] = v.x * scale;
        q[d4 * 4 + 1] = v.y * scale;
        q[d4 * 4 + 2] = v.z * scale;
        q[d4 * 4 + 3] = v.w * scale;
    }
    float o[HD_];
    #pragma unroll
    for (int d = 0; d < HD_; d++) o[d] = 0.f;
    float m = -3.0e38f, l = 0.f;

    __shared__ float ks[64 * HD_];
    __shared__ float vs[64 * HD_];

    for (int t = 0; t < N_ / 64; t++) {
        __syncthreads();
        const float4* kg = (const float4*)(g_k + base + (size_t)t * 64 * HD_);
        const float4* vg = (const float4*)(g_v + base + (size_t)t * 64 * HD_);
        #pragma unroll
        for (int i = 0; i < 8; i++) {
            int idx = threadIdx.x + i * 128;
            ((float4*)ks)[idx] = kg[idx];
            ((float4*)vs)[idx] = vg[idx];
        }
        __syncthreads();

        for (int j = 0; j < 64; j++) {
            float s = 0.f;
            const float4* kr = (const float4*)&ks[j * HD_];
            #pragma unroll
            for (int d4 = 0; d4 < 16; d4++) {
                float4 kv = kr[d4];
                s = fmaf(q[d4 * 4 + 0], kv.x, s);
                s = fmaf(q[d4 * 4 + 1], kv.y, s);
                s = fmaf(q[d4 * 4 + 2], kv.z, s);
                s = fmaf(q[d4 * 4 + 3], kv.w, s);
            }
            float mn = fmaxf(m, s);
            if (mn > m) {
                float corr = __expf(m - mn);
                l *= corr;
                #pragma unroll
                for (int d = 0; d < HD_; d++) o[d] *= corr;
                m = mn;
            }
            float p = __expf(s - m);
            l += p;
            const float4* vr = (const float4*)&vs[j * HD_];
            #pragma unroll
            for (int d4 = 0; d4 < 16; d4++) {
                float4 vv = vr[d4];
                o[d4 * 4 + 0] = fmaf(p, vv.x, o[d4 * 4 + 0]);
                o[d4 * 4 + 1] = fmaf(p, vv.y, o[d4 * 4 + 1]);
                o[d4 * 4 + 2] = fmaf(p, vv.z, o[d4 * 4 + 2]);
                o[d4 * 4 + 3] = fmaf(p, vv.w, o[d4 * 4 + 3]);
            }
        }
    }

    float inv = 1.0f / l;
    size_t orow = ((size_t)(bh >> 4) * N_ + qi) * D_ + (size_t)(bh & 15) * HD_;
    #pragma unroll
    for (int d4 = 0; d4 < 16; d4++) {
        float4 v;
        v.x = o[d4 * 4 + 0] * inv;
        v.y = o[d4 * 4 + 1] * inv;
        v.z = o[d4 * 4 + 2] * inv;
        v.w = o[d4 * 4 + 3] * inv;
        *(float4*)&g_o[orow + d4 * 4] = v;
    }
}

// ---------------- launch ----------------------------------------------------
extern "C" void kernel_launch(void* const* d_in, const int* in_sizes, int n_in,
                              void* d_out, int out_size)
{
    const float* x       = (const float*)d_in[0];
    const float* Wqkv    = (const float*)d_in[1];
    const float* bqkv    = (const float*)d_in[2];
    const float* Wout    = (const float*)d_in[3];
    const float* bout    = (const float*)d_in[4];
    const float* q_scale = (const float*)d_in[5];
    const float* k_scale = (const float*)d_in[6];
    float* out = (float*)d_out;

    float *qkv_p = nullptr, *o_p = nullptr;
    cudaGetSymbolAddress((void**)&qkv_p, g_qkv);
    cudaGetSymbolAddress((void**)&o_p,   g_o);

    cudaFuncSetAttribute(gemm_tf32_bias,
                         cudaFuncAttributeMaxDynamicSharedMemorySize,
                         GEMM_SMEM_BYTES);

    // 1. RoPE cos/sin tables
    rope_tables_kernel<<<(N_ * 32 + 255) / 256, 256>>>();

    // 2. QKV GEMM: [8192,1024] @ [1024,3072] + bias  (tf32 tensor cores)
    dim3 g1(N3_ / GBN, M_ / GBM);
    gemm_tf32_bias<<<g1, 256, GEMM_SMEM_BYTES>>>(x, Wqkv, bqkv, qkv_p, M_, N3_, D_);

    // 3. RMSNorm + RoPE + reshape
    rmsnorm_rope_kernel<<<(B_ * N_ * H_) / 8, 256>>>(q_scale, k_scale);

    // 4. Flash attention
    attn_kernel<<<dim3(N_ / 128, B_ * H_), 128>>>();

    // 5. Output GEMM: [8192,1024] @ [1024,1024] + bias  (tf32 tensor cores)
    dim3 g2(D_ / GBN, M_ / GBM);
    gemm_tf32_bias<<<g2, 256, GEMM_SMEM_BYTES>>>(o_p, Wout, bout, out, M_, D_, D_);
}

// round 3
// speedup vs baseline: 3.1673x; 2.0763x over previous
#include <cuda_runtime.h>
#include <math.h>

// Problem dims (fixed)
#define B_  8
#define N_  1024
#define D_  1024
#define H_  16
#define HD_ 64
#define M_  (B_ * N_)      // 8192 rows
#define N3_ (3 * D_)       // 3072

// ---------------- scratch (device globals; no allocation allowed) ----------
__device__ float g_qkv[(size_t)M_ * N3_];          // 96 MB
__device__ float g_q  [(size_t)B_ * H_ * N_ * HD_]; // 33.5 MB, [b,h,n,d]
__device__ float g_k  [(size_t)B_ * H_ * N_ * HD_];
__device__ float g_v  [(size_t)B_ * H_ * N_ * HD_];
__device__ float g_o  [(size_t)M_ * D_];            // 32 MB, [b*n, h*hd+d]
__device__ float g_cos[N_ * 32];
__device__ float g_sin[N_ * 32];

__device__ __forceinline__ unsigned f2tf32(float f) {
    unsigned u;
    asm("cvt.rna.tf32.f32 %0, %1;" : "=r"(u) : "f"(f));
    return u;
}

#define MMA_TF32(d0,d1,d2,d3,a0,a1,a2,a3,b0,b1)                          \
    asm volatile(                                                         \
        "mma.sync.aligned.m16n8k8.row.col.f32.tf32.tf32.f32 "             \
        "{%0,%1,%2,%3},{%4,%5,%6,%7},{%8,%9},{%0,%1,%2,%3};\n"            \
        : "+f"(d0), "+f"(d1), "+f"(d2), "+f"(d3)                          \
        : "r"(a0), "r"(a1), "r"(a2), "r"(a3), "r"(b0), "r"(b1))

// ---------------- RoPE tables ---------------------------------------------
__global__ void rope_tables_kernel() {
    int i = blockIdx.x * blockDim.x + threadIdx.x;
    if (i >= N_ * 32) return;
    int n = i >> 5, j = i & 31;
    int pos = (j < 16) ? (n >> 5) : (n & 31);   // row idx or col idx (side=32)
    int jj  = (j < 16) ? j : (j - 16);
    double invf = pow(10000.0, -(double)jj / 16.0);
    double ang  = (double)pos * invf;
    g_cos[i] = (float)cos(ang);
    g_sin[i] = (float)sin(ang);
}

// ====================== tf32 tensor-core GEMM + bias ========================
#define GBM 128
#define GBN 256
#define GBK 16
#define ASTRIDE 20
#define BSTRIDE 260
#define A_ELEMS (GBM * ASTRIDE)
#define B_ELEMS (GBK * BSTRIDE)
#define GEMM_SMEM_BYTES ((2 * A_ELEMS + 2 * B_ELEMS) * 4)

__global__ __launch_bounds__(256, 1)
void gemm_tf32_bias(const float* __restrict__ A, const float* __restrict__ Bm,
                    const float* __restrict__ bias, float* __restrict__ C,
                    int M, int N, int K)
{
    extern __shared__ unsigned sm[];
    unsigned* As = sm;                       // [2][GBM][ASTRIDE]
    unsigned* Bs = sm + 2 * A_ELEMS;         // [2][GBK][BSTRIDE]

    const int tid  = threadIdx.x;
    const int warp = tid >> 5;
    const int lane = tid & 31;
    const int wm   = warp & 1;
    const int wn   = warp >> 1;
    const int g    = lane >> 2;
    const int t    = lane & 3;
    const int brow = blockIdx.y * GBM;
    const int bcol = blockIdx.x * GBN;

    const int ar0 = tid >> 2;
    const int akc = (tid & 3) << 2;
    const int bnc = (tid & 63) << 2;
    const int bkr = tid >> 6;

    float acc[4][8][4];
    #pragma unroll
    for (int i = 0; i < 4; i++)
        #pragma unroll
        for (int j = 0; j < 8; j++)
            #pragma unroll
            for (int c = 0; c < 4; c++) acc[i][j][c] = 0.f;

    float4 la[2], lb[4];

    #pragma unroll
    for (int it = 0; it < 2; it++)
        la[it] = *(const float4*)&A[(size_t)(brow + ar0 + it * 64) * K + akc];
    #pragma unroll
    for (int it = 0; it < 4; it++)
        lb[it] = *(const float4*)&Bm[(size_t)(bkr + it * 4) * N + bcol + bnc];

    {
        unsigned* Ab = As;
        unsigned* Bb = Bs;
        #pragma unroll
        for (int it = 0; it < 2; it++) {
            uint4 v = { f2tf32(la[it].x), f2tf32(la[it].y), f2tf32(la[it].z), f2tf32(la[it].w) };
            *(uint4*)&Ab[(ar0 + it * 64) * ASTRIDE + akc] = v;
        }
        #pragma unroll
        for (int it = 0; it < 4; it++) {
            uint4 v = { f2tf32(lb[it].x), f2tf32(lb[it].y), f2tf32(lb[it].z), f2tf32(lb[it].w) };
            *(uint4*)&Bb[(bkr + it * 4) * BSTRIDE + bnc] = v;
        }
    }
    __syncthreads();

    const int T = K / GBK;
    for (int ti = 0; ti < T; ti++) {
        if (ti + 1 < T) {
            int k0 = (ti + 1) * GBK;
            #pragma unroll
            for (int it = 0; it < 2; it++)
                la[it] = *(const float4*)&A[(size_t)(brow + ar0 + it * 64) * K + k0 + akc];
            #pragma unroll
            for (int it = 0; it < 4; it++)
                lb[it] = *(const float4*)&Bm[(size_t)(k0 + bkr + it * 4) * N + bcol + bnc];
        }

        {
            const unsigned* Ab = As + (ti & 1) * A_ELEMS;
            const unsigned* Bb = Bs + (ti & 1) * B_ELEMS;
            #pragma unroll
            for (int ks = 0; ks < 2; ks++) {
                const int kb = ks * 8;
                unsigned af[4][4], bf[8][2];
                #pragma unroll
                for (int i = 0; i < 4; i++) {
                    int m0 = wm * 64 + i * 16 + g;
                    af[i][0] = Ab[(m0    ) * ASTRIDE + kb + t    ];
                    af[i][1] = Ab[(m0 + 8) * ASTRIDE + kb + t    ];
                    af[i][2] = Ab[(m0    ) * ASTRIDE + kb + t + 4];
                    af[i][3] = Ab[(m0 + 8) * ASTRIDE + kb + t + 4];
                }
                #pragma unroll
                for (int j = 0; j < 8; j++) {
                    int n0 = wn * 64 + j * 8 + g;
                    bf[j][0] = Bb[(kb + t    ) * BSTRIDE + n0];
                    bf[j][1] = Bb[(kb + t + 4) * BSTRIDE + n0];
                }
                #pragma unroll
                for (int i = 0; i < 4; i++)
                    #pragma unroll
                    for (int j = 0; j < 8; j++)
                        MMA_TF32(acc[i][j][0], acc[i][j][1], acc[i][j][2], acc[i][j][3],
                                 af[i][0], af[i][1], af[i][2], af[i][3],
                                 bf[j][0], bf[j][1]);
            }
        }

        if (ti + 1 < T) {
            unsigned* Ab = As + ((ti + 1) & 1) * A_ELEMS;
            unsigned* Bb = Bs + ((ti + 1) & 1) * B_ELEMS;
            #pragma unroll
            for (int it = 0; it < 2; it++) {
                uint4 v = { f2tf32(la[it].x), f2tf32(la[it].y), f2tf32(la[it].z), f2tf32(la[it].w) };
                *(uint4*)&Ab[(ar0 + it * 64) * ASTRIDE + akc] = v;
            }
            #pragma unroll
            for (int it = 0; it < 4; it++) {
                uint4 v = { f2tf32(lb[it].x), f2tf32(lb[it].y), f2tf32(lb[it].z), f2tf32(lb[it].w) };
                *(uint4*)&Bb[(bkr + it * 4) * BSTRIDE + bnc] = v;
            }
        }
        __syncthreads();
    }

    #pragma unroll
    for (int i = 0; i < 4; i++) {
        int row = brow + wm * 64 + i * 16 + g;
        #pragma unroll
        for (int j = 0; j < 8; j++) {
            int col = bcol + wn * 64 + j * 8 + t * 2;
            float b0 = bias[col], b1 = bias[col + 1];
            float2 v0 = { acc[i][j][0] + b0, acc[i][j][1] + b1 };
            float2 v1 = { acc[i][j][2] + b0, acc[i][j][3] + b1 };
            *(float2*)&C[(size_t)row * N + col]       = v0;
            *(float2*)&C[(size_t)(row + 8) * N + col] = v1;
        }
    }
}

// ---------------- fused RMSNorm + RoPE + reshape to [b,h,n,d] --------------
__global__ __launch_bounds__(256)
void rmsnorm_rope_kernel(const float* __restrict__ q_scale,
                         const float* __restrict__ k_scale)
{
    int gw   = (blockIdx.x * blockDim.x + threadIdx.x) >> 5;
    int lane = threadIdx.x & 31;
    int h  = gw & 15;
    int bn = gw >> 4;
    int n  = bn & (N_ - 1);
    const float* src = g_qkv + (size_t)bn * N3_;
    float cs = g_cos[n * 32 + lane];
    float sn = g_sin[n * 32 + lane];
    int bh = (bn >> 10) * H_ + h;
    size_t dst = ((size_t)bh * N_ + n) * HD_;

    {
        float t1 = src[h * HD_ + lane];
        float t2 = src[h * HD_ + lane + 32];
        float ss = t1 * t1 + t2 * t2;
        #pragma unroll
        for (int o = 16; o > 0; o >>= 1) ss += __shfl_xor_sync(0xffffffffu, ss, o);
        float rs = rsqrtf(ss * (1.0f / HD_) + 1e-6f);
        t1 *= rs * q_scale[lane];
        t2 *= rs * q_scale[lane + 32];
        g_q[dst + lane]      = t1 * cs - t2 * sn;
        g_q[dst + lane + 32] = t1 * sn + t2 * cs;
    }
    {
        float t1 = src[D_ + h * HD_ + lane];
        float t2 = src[D_ + h * HD_ + lane + 32];
        float ss = t1 * t1 + t2 * t2;
        #pragma unroll
        for (int o = 16; o > 0; o >>= 1) ss += __shfl_xor_sync(0xffffffffu, ss, o);
        float rs = rsqrtf(ss * (1.0f / HD_) + 1e-6f);
        t1 *= rs * k_scale[lane];
        t2 *= rs * k_scale[lane + 32];
        g_k[dst + lane]      = t1 * cs - t2 * sn;
        g_k[dst + lane + 32] = t1 * sn + t2 * cs;
    }
    g_v[dst + lane]      = src[2 * D_ + h * HD_ + lane];
    g_v[dst + lane + 32] = src[2 * D_ + h * HD_ + lane + 32];
}

// ============== tensor-core flash attention (tf32 mma) ======================
// CTA: 256 threads (8 warps), Br=128 query rows (16 per warp), Bc=64 keys.
// Grid: (N/128, B*H).
#define KVSTRIDE 68   // smem row stride in words (conflict-free frag LDS)

__global__ __launch_bounds__(256)
void attn_mma_kernel()
{
    __shared__ unsigned Ks[64 * KVSTRIDE];
    __shared__ unsigned Vs[64 * KVSTRIDE];

    const int tid  = threadIdx.x;
    const int warp = tid >> 5;
    const int lane = tid & 31;
    const int g    = lane >> 2;     // 0..7
    const int t    = lane & 3;      // 0..3
    const int bh   = blockIdx.y;
    const int qbase = blockIdx.x * 128 + warp * 16;   // first q row of this warp
    const size_t base = (size_t)bh * N_ * HD_;
    const float scale = 0.125f;     // 1/sqrt(64)

    // ---- load Q fragments (rows g, g+8 of warp tile), pre-scaled, tf32 ----
    unsigned qf[8][4];
    {
        const float* Q0 = g_q + base + (size_t)(qbase + g) * HD_;
        const float* Q1 = g_q + base + (size_t)(qbase + g + 8) * HD_;
        #pragma unroll
        for (int kb = 0; kb < 8; kb++) {
            qf[kb][0] = f2tf32(Q0[kb * 8 + t]     * scale);
            qf[kb][1] = f2tf32(Q1[kb * 8 + t]     * scale);
            qf[kb][2] = f2tf32(Q0[kb * 8 + t + 4] * scale);
            qf[kb][3] = f2tf32(Q1[kb * 8 + t + 4] * scale);
        }
    }

    float of[8][4];
    #pragma unroll
    for (int j = 0; j < 8; j++)
        #pragma unroll
        for (int c = 0; c < 4; c++) of[j][c] = 0.f;
    float m0 = -1e30f, m1 = -1e30f, l0 = 0.f, l1 = 0.f;

    const int srcA = (lane & 28) + (t >> 1);
    const int srcB = srcA + 2;

    for (int tile = 0; tile < N_ / 64; tile++) {
        __syncthreads();
        // load K,V tile (64x64) -> smem, converted to tf32
        {
            const float4* kg = (const float4*)(g_k + base + (size_t)tile * 64 * HD_);
            const float4* vg = (const float4*)(g_v + base + (size_t)tile * 64 * HD_);
            #pragma unroll
            for (int it = 0; it < 4; it++) {
                int i   = tid + it * 256;
                int row = i >> 4;
                int col = (i & 15) << 2;
                float4 kv = kg[i];
                float4 vv = vg[i];
                uint4 ku = { f2tf32(kv.x), f2tf32(kv.y), f2tf32(kv.z), f2tf32(kv.w) };
                uint4 vu = { f2tf32(vv.x), f2tf32(vv.y), f2tf32(vv.z), f2tf32(vv.w) };
                *(uint4*)&Ks[row * KVSTRIDE + col] = ku;
                *(uint4*)&Vs[row * KVSTRIDE + col] = vu;
            }
        }
        __syncthreads();

        // ---- S = Q K^T  (m16 x n64, k=64) ----
        float sacc[8][4];
        #pragma unroll
        for (int j = 0; j < 8; j++)
            #pragma unroll
            for (int c = 0; c < 4; c++) sacc[j][c] = 0.f;

        #pragma unroll
        for (int kb = 0; kb < 8; kb++) {
            #pragma unroll
            for (int j = 0; j < 8; j++) {
                unsigned b0 = Ks[(j * 8 + g) * KVSTRIDE + kb * 8 + t];
                unsigned b1 = Ks[(j * 8 + g) * KVSTRIDE + kb * 8 + t + 4];
                MMA_TF32(sacc[j][0], sacc[j][1], sacc[j][2], sacc[j][3],
                         qf[kb][0], qf[kb][1], qf[kb][2], qf[kb][3], b0, b1);
            }
        }

        // ---- online softmax ----
        float mx0 = -1e30f, mx1 = -1e30f;
        #pragma unroll
        for (int j = 0; j < 8; j++) {
            mx0 = fmaxf(mx0, fmaxf(sacc[j][0], sacc[j][1]));
            mx1 = fmaxf(mx1, fmaxf(sacc[j][2], sacc[j][3]));
        }
        mx0 = fmaxf(mx0, __shfl_xor_sync(0xffffffffu, mx0, 1));
        mx0 = fmaxf(mx0, __shfl_xor_sync(0xffffffffu, mx0, 2));
        mx1 = fmaxf(mx1, __shfl_xor_sync(0xffffffffu, mx1, 1));
        mx1 = fmaxf(mx1, __shfl_xor_sync(0xffffffffu, mx1, 2));

        float mn0 = fmaxf(m0, mx0);
        float mn1 = fmaxf(m1, mx1);
        float corr0 = __expf(m0 - mn0);
        float corr1 = __expf(m1 - mn1);
        m0 = mn0; m1 = mn1;

        float sum0 = 0.f, sum1 = 0.f;
        #pragma unroll
        for (int j = 0; j < 8; j++) {
            sacc[j][0] = __expf(sacc[j][0] - mn0);
            sacc[j][1] = __expf(sacc[j][1] - mn0);
            sacc[j][2] = __expf(sacc[j][2] - mn1);
            sacc[j][3] = __expf(sacc[j][3] - mn1);
            sum0 += sacc[j][0] + sacc[j][1];
            sum1 += sacc[j][2] + sacc[j][3];
        }
        sum0 += __shfl_xor_sync(0xffffffffu, sum0, 1);
        sum0 += __shfl_xor_sync(0xffffffffu, sum0, 2);
        sum1 += __shfl_xor_sync(0xffffffffu, sum1, 1);
        sum1 += __shfl_xor_sync(0xffffffffu, sum1, 2);
        l0 = l0 * corr0 + sum0;
        l1 = l1 * corr1 + sum1;

        #pragma unroll
        for (int j = 0; j < 8; j++) {
            of[j][0] *= corr0; of[j][1] *= corr0;
            of[j][2] *= corr1; of[j][3] *= corr1;
        }

        // ---- O += P V  (k-dim = keys, 8 chunks of 8) ----
        #pragma unroll
        for (int j = 0; j < 8; j++) {
            // convert P C-frag -> A-frag via shuffles
            float e0 = __shfl_sync(0xffffffffu, sacc[j][0], srcA);
            float e1 = __shfl_sync(0xffffffffu, sacc[j][1], srcA);
            float f0 = __shfl_sync(0xffffffffu, sacc[j][0], srcB);
            float f1 = __shfl_sync(0xffffffffu, sacc[j][1], srcB);
            float e2 = __shfl_sync(0xffffffffu, sacc[j][2], srcA);
            float e3 = __shfl_sync(0xffffffffu, sacc[j][3], srcA);
            float f2 = __shfl_sync(0xffffffffu, sacc[j][2], srcB);
            float f3 = __shfl_sync(0xffffffffu, sacc[j][3], srcB);
            unsigned pa0 = f2tf32((t & 1) ? e1 : e0);   // P[g][j8+t]
            unsigned pa1 = f2tf32((t & 1) ? e3 : e2);   // P[g+8][j8+t]
            unsigned pa2 = f2tf32((t & 1) ? f1 : f0);   // P[g][j8+t+4]
            unsigned pa3 = f2tf32((t & 1) ? f3 : f2);   // P[g+8][j8+t+4]

            #pragma unroll
            for (int jj = 0; jj < 8; jj++) {
                unsigned b0 = Vs[(j * 8 + t)     * KVSTRIDE + jj * 8 + g];
                unsigned b1 = Vs[(j * 8 + t + 4) * KVSTRIDE + jj * 8 + g];
                MMA_TF32(of[jj][0], of[jj][1], of[jj][2], of[jj][3],
                         pa0, pa1, pa2, pa3, b0, b1);
            }
        }
    }

    // ---- epilogue: normalize, write to [b*n, h*64+d] ----
    float inv0 = 1.0f / l0;
    float inv1 = 1.0f / l1;
    const int b = bh >> 4, h = bh & 15;
    size_t row0 = ((size_t)b * N_ + qbase + g) * D_ + h * HD_;
    size_t row1 = ((size_t)b * N_ + qbase + g + 8) * D_ + h * HD_;
    #pragma unroll
    for (int j = 0; j < 8; j++) {
        int d = j * 8 + t * 2;
        float2 v0 = { of[j][0] * inv0, of[j][1] * inv0 };
        float2 v1 = { of[j][2] * inv1, of[j][3] * inv1 };
        *(float2*)&g_o[row0 + d] = v0;
        *(float2*)&g_o[row1 + d] = v1;
    }
}

// ---------------- launch ----------------------------------------------------
extern "C" void kernel_launch(void* const* d_in, const int* in_sizes, int n_in,
                              void* d_out, int out_size)
{
    const float* x       = (const float*)d_in[0];
    const float* Wqkv    = (const float*)d_in[1];
    const float* bqkv    = (const float*)d_in[2];
    const float* Wout    = (const float*)d_in[3];
    const float* bout    = (const float*)d_in[4];
    const float* q_scale = (const float*)d_in[5];
    const float* k_scale = (const float*)d_in[6];
    float* out = (float*)d_out;

    float *qkv_p = nullptr, *o_p = nullptr;
    cudaGetSymbolAddress((void**)&qkv_p, g_qkv);
    cudaGetSymbolAddress((void**)&o_p,   g_o);

    cudaFuncSetAttribute(gemm_tf32_bias,
                         cudaFuncAttributeMaxDynamicSharedMemorySize,
                         GEMM_SMEM_BYTES);

    // 1. RoPE cos/sin tables
    rope_tables_kernel<<<(N_ * 32 + 255) / 256, 256>>>();

    // 2. QKV GEMM: [8192,1024] @ [1024,3072] + bias  (tf32 tensor cores)
    dim3 g1(N3_ / GBN, M_ / GBM);
    gemm_tf32_bias<<<g1, 256, GEMM_SMEM_BYTES>>>(x, Wqkv, bqkv, qkv_p, M_, N3_, D_);

    // 3. RMSNorm + RoPE + reshape
    rmsnorm_rope_kernel<<<(B_ * N_ * H_) / 8, 256>>>(q_scale, k_scale);

    // 4. Flash attention (tensor cores)
    attn_mma_kernel<<<dim3(N_ / 128, B_ * H_), 256>>>();

    // 5. Output GEMM: [8192,1024] @ [1024,1024] + bias  (tf32 tensor cores)
    dim3 g2(D_ / GBN, M_ / GBM);
    gemm_tf32_bias<<<g2, 256, GEMM_SMEM_BYTES>>>(o_p, Wout, bout, out, M_, D_, D_);
}

// round 4
// speedup vs baseline: 3.2341x; 1.0211x over previous
#include <cuda_runtime.h>
#include <math.h>

// Problem dims (fixed)
#define B_  8
#define N_  1024
#define D_  1024
#define H_  16
#define HD_ 64
#define M_  (B_ * N_)      // 8192 rows
#define N3_ (3 * D_)       // 3072

// ---------------- scratch (device globals; no allocation allowed) ----------
__device__ float g_qkv[(size_t)M_ * N3_];
__device__ float g_q  [(size_t)B_ * H_ * N_ * HD_];
__device__ float g_k  [(size_t)B_ * H_ * N_ * HD_];
__device__ float g_v  [(size_t)B_ * H_ * N_ * HD_];
__device__ float g_o  [(size_t)M_ * D_];
__device__ float g_cos[N_ * 32];
__device__ float g_sin[N_ * 32];

__device__ __forceinline__ unsigned f2tf32(float f) {
    unsigned u;
    asm("cvt.rna.tf32.f32 %0, %1;" : "=r"(u) : "f"(f));
    return u;
}

#define MMA_TF32(d0,d1,d2,d3,a0,a1,a2,a3,b0,b1)                          \
    asm volatile(                                                         \
        "mma.sync.aligned.m16n8k8.row.col.f32.tf32.tf32.f32 "             \
        "{%0,%1,%2,%3},{%4,%5,%6,%7},{%8,%9},{%0,%1,%2,%3};\n"            \
        : "+f"(d0), "+f"(d1), "+f"(d2), "+f"(d3)                          \
        : "r"(a0), "r"(a1), "r"(a2), "r"(a3), "r"(b0), "r"(b1))

__device__ __forceinline__ void cp16(unsigned smem_addr, const void* gptr) {
    asm volatile("cp.async.cg.shared.global [%0], [%1], 16;\n"
                 :: "r"(smem_addr), "l"(gptr));
}
#define CP_COMMIT() asm volatile("cp.async.commit_group;\n")
#define CP_WAIT(n)  asm volatile("cp.async.wait_group %0;\n" :: "n"(n))

// ---------------- RoPE tables ---------------------------------------------
__global__ void rope_tables_kernel() {
    int i = blockIdx.x * blockDim.x + threadIdx.x;
    if (i >= N_ * 32) return;
    int n = i >> 5, j = i & 31;
    int pos = (j < 16) ? (n >> 5) : (n & 31);
    int jj  = (j < 16) ? j : (j - 16);
    double invf = pow(10000.0, -(double)jj / 16.0);
    double ang  = (double)pos * invf;
    g_cos[i] = (float)cos(ang);
    g_sin[i] = (float)sin(ang);
}

// ====================== tf32 tensor-core GEMM + bias ========================
// 128x256x16 block tile, 8 warps, cp.async 3-stage pipeline.
#define GBM 128
#define GBN 256
#define GBK 16
#define ASTRIDE 20
#define BSTRIDE 260
#define A_ELEMS (GBM * ASTRIDE)    // 2560 words
#define B_ELEMS (GBK * BSTRIDE)    // 4160 words
#define STAGE_ELEMS (A_ELEMS + B_ELEMS)
#define NSTAGE 3
#define GEMM_SMEM_BYTES (NSTAGE * STAGE_ELEMS * 4)   // 80640

__global__ __launch_bounds__(256, 1)
void gemm_tf32_bias(const float* __restrict__ A, const float* __restrict__ Bm,
                    const float* __restrict__ bias, float* __restrict__ C,
                    int M, int N, int K)
{
    extern __shared__ float sm[];
    unsigned smem_base;
    {
        void* p = sm;
        smem_base = (unsigned)__cvta_generic_to_shared(p);
    }

    const int tid  = threadIdx.x;
    const int warp = tid >> 5;
    const int lane = tid & 31;
    const int wm   = warp & 1;
    const int wn   = warp >> 1;
    const int g    = lane >> 2;
    const int t    = lane & 3;
    const int brow = blockIdx.y * GBM;
    const int bcol = blockIdx.x * GBN;

    const int ar0 = tid >> 2;          // 0..63
    const int akc = (tid & 3) << 2;    // k offset
    const int bnc = (tid & 63) << 2;   // col offset
    const int bkr = tid >> 6;          // 0..3

    float acc[4][8][4];
    #pragma unroll
    for (int i = 0; i < 4; i++)
        #pragma unroll
        for (int j = 0; j < 8; j++)
            #pragma unroll
            for (int c = 0; c < 4; c++) acc[i][j][c] = 0.f;

    const int T = K / GBK;

    // issue loads for stage s covering k0
    auto issue = [&](int s, int k0) {
        unsigned abase = smem_base + (s * STAGE_ELEMS) * 4;
        unsigned bbase = abase + A_ELEMS * 4;
        #pragma unroll
        for (int it = 0; it < 2; it++) {
            int r = ar0 + it * 64;
            cp16(abase + (r * ASTRIDE + akc) * 4,
                 &A[(size_t)(brow + r) * K + k0 + akc]);
        }
        #pragma unroll
        for (int it = 0; it < 4; it++) {
            int r = bkr + it * 4;
            cp16(bbase + (r * BSTRIDE + bnc) * 4,
                 &Bm[(size_t)(k0 + r) * N + bcol + bnc]);
        }
    };

    issue(0, 0);      CP_COMMIT();
    issue(1, GBK);    CP_COMMIT();

    int sc = 0;   // compute stage
    for (int ti = 0; ti < T; ti++) {
        CP_WAIT(1);
        __syncthreads();

        if (ti + 2 < T) issue((sc + 2) % NSTAGE, (ti + 2) * GBK);
        CP_COMMIT();

        const float* Ab = sm + sc * STAGE_ELEMS;
        const float* Bb = Ab + A_ELEMS;

        #pragma unroll
        for (int ks = 0; ks < 2; ks++) {
            const int kb = ks * 8;
            unsigned af[4][4], bf[8][2];
            #pragma unroll
            for (int i = 0; i < 4; i++) {
                int m0 = wm * 64 + i * 16 + g;
                af[i][0] = f2tf32(Ab[(m0    ) * ASTRIDE + kb + t    ]);
                af[i][1] = f2tf32(Ab[(m0 + 8) * ASTRIDE + kb + t    ]);
                af[i][2] = f2tf32(Ab[(m0    ) * ASTRIDE + kb + t + 4]);
                af[i][3] = f2tf32(Ab[(m0 + 8) * ASTRIDE + kb + t + 4]);
            }
            #pragma unroll
            for (int j = 0; j < 8; j++) {
                int n0 = wn * 64 + j * 8 + g;
                bf[j][0] = f2tf32(Bb[(kb + t    ) * BSTRIDE + n0]);
                bf[j][1] = f2tf32(Bb[(kb + t + 4) * BSTRIDE + n0]);
            }
            #pragma unroll
            for (int i = 0; i < 4; i++)
                #pragma unroll
                for (int j = 0; j < 8; j++)
                    MMA_TF32(acc[i][j][0], acc[i][j][1], acc[i][j][2], acc[i][j][3],
                             af[i][0], af[i][1], af[i][2], af[i][3],
                             bf[j][0], bf[j][1]);
        }

        sc = (sc + 1) % NSTAGE;
        __syncthreads();
    }

    #pragma unroll
    for (int i = 0; i < 4; i++) {
        int row = brow + wm * 64 + i * 16 + g;
        #pragma unroll
        for (int j = 0; j < 8; j++) {
            int col = bcol + wn * 64 + j * 8 + t * 2;
            float b0 = bias[col], b1 = bias[col + 1];
            float2 v0 = { acc[i][j][0] + b0, acc[i][j][1] + b1 };
            float2 v1 = { acc[i][j][2] + b0, acc[i][j][3] + b1 };
            *(float2*)&C[(size_t)row * N + col]       = v0;
            *(float2*)&C[(size_t)(row + 8) * N + col] = v1;
        }
    }
}

// ---------------- fused RMSNorm + RoPE + reshape to [b,h,n,d] --------------
__global__ __launch_bounds__(256)
void rmsnorm_rope_kernel(const float* __restrict__ q_scale,
                         const float* __restrict__ k_scale)
{
    int gw   = (blockIdx.x * blockDim.x + threadIdx.x) >> 5;
    int lane = threadIdx.x & 31;
    int h  = gw & 15;
    int bn = gw >> 4;
    int n  = bn & (N_ - 1);
    const float* src = g_qkv + (size_t)bn * N3_;
    float cs = g_cos[n * 32 + lane];
    float sn = g_sin[n * 32 + lane];
    int bh = (bn >> 10) * H_ + h;
    size_t dst = ((size_t)bh * N_ + n) * HD_;

    {
        float t1 = src[h * HD_ + lane];
        float t2 = src[h * HD_ + lane + 32];
        float ss = t1 * t1 + t2 * t2;
        #pragma unroll
        for (int o = 16; o > 0; o >>= 1) ss += __shfl_xor_sync(0xffffffffu, ss, o);
        float rs = rsqrtf(ss * (1.0f / HD_) + 1e-6f);
        t1 *= rs * q_scale[lane];
        t2 *= rs * q_scale[lane + 32];
        g_q[dst + lane]      = t1 * cs - t2 * sn;
        g_q[dst + lane + 32] = t1 * sn + t2 * cs;
    }
    {
        float t1 = src[D_ + h * HD_ + lane];
        float t2 = src[D_ + h * HD_ + lane + 32];
        float ss = t1 * t1 + t2 * t2;
        #pragma unroll
        for (int o = 16; o > 0; o >>= 1) ss += __shfl_xor_sync(0xffffffffu, ss, o);
        float rs = rsqrtf(ss * (1.0f / HD_) + 1e-6f);
        t1 *= rs * k_scale[lane];
        t2 *= rs * k_scale[lane + 32];
        g_k[dst + lane]      = t1 * cs - t2 * sn;
        g_k[dst + lane + 32] = t1 * sn + t2 * cs;
    }
    g_v[dst + lane]      = src[2 * D_ + h * HD_ + lane];
    g_v[dst + lane + 32] = src[2 * D_ + h * HD_ + lane + 32];
}

// ============== tensor-core flash attention (tf32 mma) ======================
// CTA: 128 threads (4 warps). Br=128 rows -> 32 rows/warp (2 m16 tiles).
// Bc=64 keys/tile. Each B fragment LDS feeds 2 MMAs.
#define KVSTRIDE 68

__global__ __launch_bounds__(128)
void attn_mma_kernel()
{
    __shared__ unsigned Ks[64 * KVSTRIDE];
    __shared__ unsigned Vs[64 * KVSTRIDE];

    const int tid  = threadIdx.x;
    const int warp = tid >> 5;
    const int lane = tid & 31;
    const int g    = lane >> 2;     // 0..7
    const int t    = lane & 3;      // 0..3
    const int bh   = blockIdx.y;
    const int qbase = blockIdx.x * 128 + warp * 32;   // 32 rows per warp
    const size_t base = (size_t)bh * N_ * HD_;
    const float scale = 0.125f;

    // ---- load Q fragments for 2 m-tiles, pre-scaled, tf32 ----
    unsigned qf[2][8][4];
    #pragma unroll
    for (int mt = 0; mt < 2; mt++) {
        const float* Q0 = g_q + base + (size_t)(qbase + mt * 16 + g) * HD_;
        const float* Q1 = Q0 + 8 * HD_;
        #pragma unroll
        for (int kb = 0; kb < 8; kb++) {
            qf[mt][kb][0] = f2tf32(Q0[kb * 8 + t]     * scale);
            qf[mt][kb][1] = f2tf32(Q1[kb * 8 + t]     * scale);
            qf[mt][kb][2] = f2tf32(Q0[kb * 8 + t + 4] * scale);
            qf[mt][kb][3] = f2tf32(Q1[kb * 8 + t + 4] * scale);
        }
    }

    float of[2][8][4];
    #pragma unroll
    for (int mt = 0; mt < 2; mt++)
        #pragma unroll
        for (int j = 0; j < 8; j++)
            #pragma unroll
            for (int c = 0; c < 4; c++) of[mt][j][c] = 0.f;
    float mrow[2][2] = {{-1e30f, -1e30f}, {-1e30f, -1e30f}};
    float lrow[2][2] = {{0.f, 0.f}, {0.f, 0.f}};

    const int srcA = (lane & 28) + (t >> 1);
    const int srcB = srcA + 2;

    for (int tile = 0; tile < N_ / 64; tile++) {
        __syncthreads();
        {
            const float4* kg = (const float4*)(g_k + base + (size_t)tile * 64 * HD_);
            const float4* vg = (const float4*)(g_v + base + (size_t)tile * 64 * HD_);
            #pragma unroll
            for (int it = 0; it < 8; it++) {
                int i   = tid + it * 128;
                int row = i >> 4;
                int col = (i & 15) << 2;
                float4 kv = kg[i];
                float4 vv = vg[i];
                uint4 ku = { f2tf32(kv.x), f2tf32(kv.y), f2tf32(kv.z), f2tf32(kv.w) };
                uint4 vu = { f2tf32(vv.x), f2tf32(vv.y), f2tf32(vv.z), f2tf32(vv.w) };
                *(uint4*)&Ks[row * KVSTRIDE + col] = ku;
                *(uint4*)&Vs[row * KVSTRIDE + col] = vu;
            }
        }
        __syncthreads();

        // ---- S = Q K^T for both m-tiles ----
        float sacc[2][8][4];
        #pragma unroll
        for (int mt = 0; mt < 2; mt++)
            #pragma unroll
            for (int j = 0; j < 8; j++)
                #pragma unroll
                for (int c = 0; c < 4; c++) sacc[mt][j][c] = 0.f;

        #pragma unroll
        for (int kb = 0; kb < 8; kb++) {
            #pragma unroll
            for (int j = 0; j < 8; j++) {
                unsigned b0 = Ks[(j * 8 + g) * KVSTRIDE + kb * 8 + t];
                unsigned b1 = Ks[(j * 8 + g) * KVSTRIDE + kb * 8 + t + 4];
                MMA_TF32(sacc[0][j][0], sacc[0][j][1], sacc[0][j][2], sacc[0][j][3],
                         qf[0][kb][0], qf[0][kb][1], qf[0][kb][2], qf[0][kb][3], b0, b1);
                MMA_TF32(sacc[1][j][0], sacc[1][j][1], sacc[1][j][2], sacc[1][j][3],
                         qf[1][kb][0], qf[1][kb][1], qf[1][kb][2], qf[1][kb][3], b0, b1);
            }
        }

        // ---- online softmax per m-tile ----
        #pragma unroll
        for (int mt = 0; mt < 2; mt++) {
            float mx0 = -1e30f, mx1 = -1e30f;
            #pragma unroll
            for (int j = 0; j < 8; j++) {
                mx0 = fmaxf(mx0, fmaxf(sacc[mt][j][0], sacc[mt][j][1]));
                mx1 = fmaxf(mx1, fmaxf(sacc[mt][j][2], sacc[mt][j][3]));
            }
            mx0 = fmaxf(mx0, __shfl_xor_sync(0xffffffffu, mx0, 1));
            mx0 = fmaxf(mx0, __shfl_xor_sync(0xffffffffu, mx0, 2));
            mx1 = fmaxf(mx1, __shfl_xor_sync(0xffffffffu, mx1, 1));
            mx1 = fmaxf(mx1, __shfl_xor_sync(0xffffffffu, mx1, 2));

            float mn0 = fmaxf(mrow[mt][0], mx0);
            float mn1 = fmaxf(mrow[mt][1], mx1);
            float corr0 = __expf(mrow[mt][0] - mn0);
            float corr1 = __expf(mrow[mt][1] - mn1);
            mrow[mt][0] = mn0; mrow[mt][1] = mn1;

            float sum0 = 0.f, sum1 = 0.f;
            #pragma unroll
            for (int j = 0; j < 8; j++) {
                sacc[mt][j][0] = __expf(sacc[mt][j][0] - mn0);
                sacc[mt][j][1] = __expf(sacc[mt][j][1] - mn0);
                sacc[mt][j][2] = __expf(sacc[mt][j][2] - mn1);
                sacc[mt][j][3] = __expf(sacc[mt][j][3] - mn1);
                sum0 += sacc[mt][j][0] + sacc[mt][j][1];
                sum1 += sacc[mt][j][2] + sacc[mt][j][3];
            }
            sum0 += __shfl_xor_sync(0xffffffffu, sum0, 1);
            sum0 += __shfl_xor_sync(0xffffffffu, sum0, 2);
            sum1 += __shfl_xor_sync(0xffffffffu, sum1, 1);
            sum1 += __shfl_xor_sync(0xffffffffu, sum1, 2);
            lrow[mt][0] = lrow[mt][0] * corr0 + sum0;
            lrow[mt][1] = lrow[mt][1] * corr1 + sum1;

            #pragma unroll
            for (int j = 0; j < 8; j++) {
                of[mt][j][0] *= corr0; of[mt][j][1] *= corr0;
                of[mt][j][2] *= corr1; of[mt][j][3] *= corr1;
            }
        }

        // ---- O += P V ----
        #pragma unroll
        for (int j = 0; j < 8; j++) {
            unsigned pa[2][4];
            #pragma unroll
            for (int mt = 0; mt < 2; mt++) {
                float e0 = __shfl_sync(0xffffffffu, sacc[mt][j][0], srcA);
                float e1 = __shfl_sync(0xffffffffu, sacc[mt][j][1], srcA);
                float f0 = __shfl_sync(0xffffffffu, sacc[mt][j][0], srcB);
                float f1 = __shfl_sync(0xffffffffu, sacc[mt][j][1], srcB);
                float e2 = __shfl_sync(0xffffffffu, sacc[mt][j][2], srcA);
                float e3 = __shfl_sync(0xffffffffu, sacc[mt][j][3], srcA);
                float f2 = __shfl_sync(0xffffffffu, sacc[mt][j][2], srcB);
                float f3 = __shfl_sync(0xffffffffu, sacc[mt][j][3], srcB);
                pa[mt][0] = f2tf32((t & 1) ? e1 : e0);
                pa[mt][1] = f2tf32((t & 1) ? e3 : e2);
                pa[mt][2] = f2tf32((t & 1) ? f1 : f0);
                pa[mt][3] = f2tf32((t & 1) ? f3 : f2);
            }
            #pragma unroll
            for (int jj = 0; jj < 8; jj++) {
                unsigned b0 = Vs[(j * 8 + t)     * KVSTRIDE + jj * 8 + g];
                unsigned b1 = Vs[(j * 8 + t + 4) * KVSTRIDE + jj * 8 + g];
                MMA_TF32(of[0][jj][0], of[0][jj][1], of[0][jj][2], of[0][jj][3],
                         pa[0][0], pa[0][1], pa[0][2], pa[0][3], b0, b1);
                MMA_TF32(of[1][jj][0], of[1][jj][1], of[1][jj][2], of[1][jj][3],
                         pa[1][0], pa[1][1], pa[1][2], pa[1][3], b0, b1);
            }
        }
    }

    // ---- epilogue ----
    const int b = bh >> 4, h = bh & 15;
    #pragma unroll
    for (int mt = 0; mt < 2; mt++) {
        float inv0 = 1.0f / lrow[mt][0];
        float inv1 = 1.0f / lrow[mt][1];
        size_t row0 = ((size_t)b * N_ + qbase + mt * 16 + g) * D_ + h * HD_;
        size_t row1 = row0 + (size_t)8 * D_;
        #pragma unroll
        for (int j = 0; j < 8; j++) {
            int d = j * 8 + t * 2;
            float2 v0 = { of[mt][j][0] * inv0, of[mt][j][1] * inv0 };
            float2 v1 = { of[mt][j][2] * inv1, of[mt][j][3] * inv1 };
            *(float2*)&g_o[row0 + d] = v0;
            *(float2*)&g_o[row1 + d] = v1;
        }
    }
}

// ---------------- launch ----------------------------------------------------
extern "C" void kernel_launch(void* const* d_in, const int* in_sizes, int n_in,
                              void* d_out, int out_size)
{
    const float* x       = (const float*)d_in[0];
    const float* Wqkv    = (const float*)d_in[1];
    const float* bqkv    = (const float*)d_in[2];
    const float* Wout    = (const float*)d_in[3];
    const float* bout    = (const float*)d_in[4];
    const float* q_scale = (const float*)d_in[5];
    const float* k_scale = (const float*)d_in[6];
    float* out = (float*)d_out;

    float *qkv_p = nullptr, *o_p = nullptr;
    cudaGetSymbolAddress((void**)&qkv_p, g_qkv);
    cudaGetSymbolAddress((void**)&o_p,   g_o);

    cudaFuncSetAttribute(gemm_tf32_bias,
                         cudaFuncAttributeMaxDynamicSharedMemorySize,
                         GEMM_SMEM_BYTES);

    rope_tables_kernel<<<(N_ * 32 + 255) / 256, 256>>>();

    dim3 g1(N3_ / GBN, M_ / GBM);
    gemm_tf32_bias<<<g1, 256, GEMM_SMEM_BYTES>>>(x, Wqkv, bqkv, qkv_p, M_, N3_, D_);

    rmsnorm_rope_kernel<<<(B_ * N_ * H_) / 8, 256>>>(q_scale, k_scale);

    attn_mma_kernel<<<dim3(N_ / 128, B_ * H_), 128>>>();

    dim3 g2(D_ / GBN, M_ / GBM);
    gemm_tf32_bias<<<g2, 256, GEMM_SMEM_BYTES>>>(o_p, Wout, bout, out, M_, D_, D_);
}

// round 5
// speedup vs baseline: 6.3117x; 1.9516x over previous
#include <cuda_runtime.h>
#include <cuda_fp16.h>
#include <math.h>

#define B_  8
#define N_  1024
#define D_  1024
#define H_  16
#define HD_ 64
#define M_  (B_ * N_)
#define N3_ (3 * D_)

// ---------------- scratch ----------------------------------------------------
__device__ float  g_qkv[(size_t)M_ * N3_];            // fp32 QKV output
__device__ __half g_xh [(size_t)M_ * D_];             // fp16 x
__device__ __half g_wqkvh[(size_t)D_ * N3_];          // fp16 Wqkv
__device__ __half g_wouth[(size_t)D_ * D_];           // fp16 Wout
__device__ __half g_qh [(size_t)B_ * H_ * N_ * HD_];  // fp16 q (pre-scaled)
__device__ __half g_kh [(size_t)B_ * H_ * N_ * HD_];
__device__ __half g_vh [(size_t)B_ * H_ * N_ * HD_];
__device__ __half g_oh [(size_t)M_ * D_];             // fp16 attention out
__device__ float  g_cos[N_ * 32];
__device__ float  g_sin[N_ * 32];

// ---------------- helpers -----------------------------------------------------
#define MMA_F16(d0,d1,d2,d3,a0,a1,a2,a3,b0,b1)                            \
    asm volatile(                                                          \
        "mma.sync.aligned.m16n8k16.row.col.f32.f16.f16.f32 "               \
        "{%0,%1,%2,%3},{%4,%5,%6,%7},{%8,%9},{%0,%1,%2,%3};\n"             \
        : "+f"(d0), "+f"(d1), "+f"(d2), "+f"(d3)                           \
        : "r"(a0), "r"(a1), "r"(a2), "r"(a3), "r"(b0), "r"(b1))

__device__ __forceinline__ void ldm_x4(unsigned& r0, unsigned& r1,
                                       unsigned& r2, unsigned& r3, unsigned a) {
    asm volatile("ldmatrix.sync.aligned.m8n8.x4.shared.b16 {%0,%1,%2,%3}, [%4];\n"
                 : "=r"(r0), "=r"(r1), "=r"(r2), "=r"(r3) : "r"(a));
}
__device__ __forceinline__ void ldm_x4_t(unsigned& r0, unsigned& r1,
                                         unsigned& r2, unsigned& r3, unsigned a) {
    asm volatile("ldmatrix.sync.aligned.m8n8.x4.trans.shared.b16 {%0,%1,%2,%3}, [%4];\n"
                 : "=r"(r0), "=r"(r1), "=r"(r2), "=r"(r3) : "r"(a));
}
__device__ __forceinline__ void cp16(unsigned smem_addr, const void* gptr) {
    asm volatile("cp.async.cg.shared.global [%0], [%1], 16;\n"
                 :: "r"(smem_addr), "l"(gptr));
}
#define CP_COMMIT() asm volatile("cp.async.commit_group;\n")
#define CP_WAIT(n)  asm volatile("cp.async.wait_group %0;\n" :: "n"(n))

__device__ __forceinline__ unsigned packh2(float a, float b) {
    __half2 h = __floats2half2_rn(a, b);
    return *(unsigned*)&h;
}

// ---------------- fp32 -> fp16 conversion -------------------------------------
__global__ void f2h_kernel(const float* __restrict__ src, __half* __restrict__ dst,
                           int n4) {
    int i = blockIdx.x * blockDim.x + threadIdx.x;
    if (i >= n4) return;
    float4 v = ((const float4*)src)[i];
    __half2 h0 = __floats2half2_rn(v.x, v.y);
    __half2 h1 = __floats2half2_rn(v.z, v.w);
    ((__half2*)dst)[i * 2]     = h0;
    ((__half2*)dst)[i * 2 + 1] = h1;
}

// ---------------- RoPE tables --------------------------------------------------
__global__ void rope_tables_kernel() {
    int i = blockIdx.x * blockDim.x + threadIdx.x;
    if (i >= N_ * 32) return;
    int n = i >> 5, j = i & 31;
    int pos = (j < 16) ? (n >> 5) : (n & 31);
    int jj  = (j < 16) ? j : (j - 16);
    double invf = pow(10000.0, -(double)jj / 16.0);
    double ang  = (double)pos * invf;
    g_cos[i] = (float)cos(ang);
    g_sin[i] = (float)sin(ang);
}

// ====================== fp16 tensor-core GEMM + bias ===========================
// C[M,N](fp32) = A[M,K](fp16) @ B[K,N](fp16) + bias.
// Block 128x256x32, 8 warps (2x4), warp tile 64x64, cp.async 3-stage, ldmatrix.
#define GBM 128
#define GBN 256
#define GBK 32
#define AST 40     // A smem row stride (halves)
#define BST 264    // B smem row stride (halves)
#define A_HALF (GBM * AST)     // 5120
#define B_HALF (GBK * BST)     // 8448
#define STG_HALF (A_HALF + B_HALF)
#define NSTAGE 3
#define GEMM_SMEM_BYTES (NSTAGE * STG_HALF * 2)    // 81408

__global__ __launch_bounds__(256, 1)
void gemm_f16_bias(const __half* __restrict__ A, const __half* __restrict__ Bm,
                   const float* __restrict__ bias, float* __restrict__ C,
                   int M, int N, int K)
{
    extern __shared__ __half sm[];
    const unsigned smem_base = (unsigned)__cvta_generic_to_shared(sm);

    const int tid  = threadIdx.x;
    const int warp = tid >> 5;
    const int lane = tid & 31;
    const int wm   = warp & 1;
    const int wn   = warp >> 1;
    const int g    = lane >> 2;
    const int t    = lane & 3;
    const int brow = blockIdx.y * GBM;
    const int bcol = blockIdx.x * GBN;

    float acc[4][8][4];
    #pragma unroll
    for (int i = 0; i < 4; i++)
        #pragma unroll
        for (int j = 0; j < 8; j++)
            #pragma unroll
            for (int c = 0; c < 4; c++) acc[i][j][c] = 0.f;

    const int T = K / GBK;

    auto issue = [&](int s, int k0) {
        unsigned abase = smem_base + (s * STG_HALF) * 2;
        unsigned bbase = abase + A_HALF * 2;
        #pragma unroll
        for (int it = 0; it < 2; it++) {
            int idx = tid + it * 256;
            int row = idx >> 2, cc = (idx & 3) * 8;
            cp16(abase + (row * AST + cc) * 2,
                 &A[(size_t)(brow + row) * K + k0 + cc]);
        }
        #pragma unroll
        for (int it = 0; it < 4; it++) {
            int idx = tid + it * 256;
            int row = idx >> 5, cc = (idx & 31) * 8;
            cp16(bbase + (row * BST + cc) * 2,
                 &Bm[(size_t)(k0 + row) * N + bcol + cc]);
        }
    };

    issue(0, 0);     CP_COMMIT();
    issue(1, GBK);   CP_COMMIT();

    // ldmatrix addresses (per lane, fixed parts)
    const int a_r = (lane & 15);          // row within 16
    const int a_c = (lane >> 4) * 8;      // col offset
    int sc = 0;
    for (int ti = 0; ti < T; ti++) {
        CP_WAIT(1);
        __syncthreads();
        if (ti + 2 < T) issue((sc + 2) % NSTAGE, (ti + 2) * GBK);
        CP_COMMIT();

        unsigned abase = smem_base + (sc * STG_HALF) * 2;
        unsigned bbase = abase + A_HALF * 2;

        #pragma unroll
        for (int ks = 0; ks < 2; ks++) {
            const int kb = ks * 16;
            unsigned af[4][4], bf[8][2];
            #pragma unroll
            for (int i = 0; i < 4; i++) {
                int m0 = wm * 64 + i * 16;
                ldm_x4(af[i][0], af[i][1], af[i][2], af[i][3],
                       abase + ((m0 + a_r) * AST + kb + a_c) * 2);
            }
            #pragma unroll
            for (int jp = 0; jp < 4; jp++) {
                int n0 = wn * 64 + jp * 16;
                unsigned r0, r1, r2, r3;
                ldm_x4_t(r0, r1, r2, r3,
                         bbase + ((kb + a_r) * BST + n0 + a_c) * 2);
                bf[jp * 2][0]     = r0; bf[jp * 2][1]     = r1;
                bf[jp * 2 + 1][0] = r2; bf[jp * 2 + 1][1] = r3;
            }
            #pragma unroll
            for (int i = 0; i < 4; i++)
                #pragma unroll
                for (int j = 0; j < 8; j++)
                    MMA_F16(acc[i][j][0], acc[i][j][1], acc[i][j][2], acc[i][j][3],
                            af[i][0], af[i][1], af[i][2], af[i][3],
                            bf[j][0], bf[j][1]);
        }
        sc = (sc + 1) % NSTAGE;
        __syncthreads();
    }

    #pragma unroll
    for (int i = 0; i < 4; i++) {
        int row = brow + wm * 64 + i * 16 + g;
        #pragma unroll
        for (int j = 0; j < 8; j++) {
            int col = bcol + wn * 64 + j * 8 + t * 2;
            float b0 = bias[col], b1 = bias[col + 1];
            float2 v0 = { acc[i][j][0] + b0, acc[i][j][1] + b1 };
            float2 v1 = { acc[i][j][2] + b0, acc[i][j][3] + b1 };
            *(float2*)&C[(size_t)row * N + col]       = v0;
            *(float2*)&C[(size_t)(row + 8) * N + col] = v1;
        }
    }
}

// ---------------- fused RMSNorm + RoPE + reshape (fp16 out, q pre-scaled) ------
__global__ __launch_bounds__(256)
void rmsnorm_rope_kernel(const float* __restrict__ q_scale,
                         const float* __restrict__ k_scale)
{
    int gw   = (blockIdx.x * blockDim.x + threadIdx.x) >> 5;
    int lane = threadIdx.x & 31;
    int h  = gw & 15;
    int bn = gw >> 4;
    int n  = bn & (N_ - 1);
    const float* src = g_qkv + (size_t)bn * N3_;
    float cs = g_cos[n * 32 + lane];
    float sn = g_sin[n * 32 + lane];
    int bh = (bn >> 10) * H_ + h;
    size_t dst = ((size_t)bh * N_ + n) * HD_;

    {
        float t1 = src[h * HD_ + lane];
        float t2 = src[h * HD_ + lane + 32];
        float ss = t1 * t1 + t2 * t2;
        #pragma unroll
        for (int o = 16; o > 0; o >>= 1) ss += __shfl_xor_sync(0xffffffffu, ss, o);
        float rs = rsqrtf(ss * (1.0f / HD_) + 1e-6f) * 0.125f;  // fold 1/sqrt(64)
        t1 *= rs * q_scale[lane];
        t2 *= rs * q_scale[lane + 32];
        g_qh[dst + lane]      = __float2half(t1 * cs - t2 * sn);
        g_qh[dst + lane + 32] = __float2half(t1 * sn + t2 * cs);
    }
    {
        float t1 = src[D_ + h * HD_ + lane];
        float t2 = src[D_ + h * HD_ + lane + 32];
        float ss = t1 * t1 + t2 * t2;
        #pragma unroll
        for (int o = 16; o > 0; o >>= 1) ss += __shfl_xor_sync(0xffffffffu, ss, o);
        float rs = rsqrtf(ss * (1.0f / HD_) + 1e-6f);
        t1 *= rs * k_scale[lane];
        t2 *= rs * k_scale[lane + 32];
        g_kh[dst + lane]      = __float2half(t1 * cs - t2 * sn);
        g_kh[dst + lane + 32] = __float2half(t1 * sn + t2 * cs);
    }
    g_vh[dst + lane]      = __float2half(src[2 * D_ + h * HD_ + lane]);
    g_vh[dst + lane + 32] = __float2half(src[2 * D_ + h * HD_ + lane + 32]);
}

// ================ fp16 tensor-core flash attention =============================
// CTA: 128 threads (4 warps), Br=128 (32 rows/warp, 2 m16 tiles), Bc=64.
// K/V tiles double-buffered via cp.async; ldmatrix fragments; P stays in regs.
#define KVST 72   // smem row stride in halves (144B)
#define KV_TILE_HALF (64 * KVST)
#define ATTN_SMEM_BYTES (4 * KV_TILE_HALF * 2)   // 2 bufs x (K+V) = 73728

__global__ __launch_bounds__(128)
void attn_f16_kernel()
{
    extern __shared__ __half asm_[];
    const unsigned smem_base = (unsigned)__cvta_generic_to_shared(asm_);

    const int tid  = threadIdx.x;
    const int warp = tid >> 5;
    const int lane = tid & 31;
    const int g    = lane >> 2;
    const int t    = lane & 3;
    const int bh   = blockIdx.y;
    const int qbase = blockIdx.x * 128 + warp * 32;
    const size_t base = (size_t)bh * N_ * HD_;

    // ---- Q fragments from gmem (pre-scaled fp16) ----
    unsigned qf[2][4][4];
    #pragma unroll
    for (int mt = 0; mt < 2; mt++) {
        const __half* Q0 = g_qh + base + (size_t)(qbase + mt * 16 + g) * HD_;
        const __half* Q1 = Q0 + 8 * HD_;
        #pragma unroll
        for (int kk = 0; kk < 4; kk++) {
            qf[mt][kk][0] = *(const unsigned*)&Q0[kk * 16 + 2 * t];
            qf[mt][kk][1] = *(const unsigned*)&Q1[kk * 16 + 2 * t];
            qf[mt][kk][2] = *(const unsigned*)&Q0[kk * 16 + 8 + 2 * t];
            qf[mt][kk][3] = *(const unsigned*)&Q1[kk * 16 + 8 + 2 * t];
        }
    }

    float of[2][8][4];
    #pragma unroll
    for (int mt = 0; mt < 2; mt++)
        #pragma unroll
        for (int j = 0; j < 8; j++)
            #pragma unroll
            for (int c = 0; c < 4; c++) of[mt][j][c] = 0.f;
    float mrow[2][2] = {{-1e30f, -1e30f}, {-1e30f, -1e30f}};
    float lrow[2][2] = {{0.f, 0.f}, {0.f, 0.f}};

    auto issue_tile = [&](int buf, int tile) {
        unsigned kb = smem_base + buf * KV_TILE_HALF * 2;
        unsigned vb = smem_base + (2 + buf) * KV_TILE_HALF * 2;
        const __half* kg = g_kh + base + (size_t)tile * 64 * HD_;
        const __half* vg = g_vh + base + (size_t)tile * 64 * HD_;
        #pragma unroll
        for (int it = 0; it < 4; it++) {
            int idx = tid + it * 128;
            int row = idx >> 3, cc = (idx & 7) * 8;
            cp16(kb + (row * KVST + cc) * 2, kg + row * HD_ + cc);
            cp16(vb + (row * KVST + cc) * 2, vg + row * HD_ + cc);
        }
    };

    issue_tile(0, 0);
    CP_COMMIT();

    const int lr = lane & 15;           // ldmatrix row-part
    const int lc = (lane >> 4) * 8;     // ldmatrix col-part

    for (int tile = 0; tile < N_ / 64; tile++) {
        if (tile + 1 < N_ / 64) issue_tile((tile + 1) & 1, tile + 1);
        CP_COMMIT();
        CP_WAIT(1);
        __syncthreads();

        unsigned kbuf = smem_base + (tile & 1) * KV_TILE_HALF * 2;
        unsigned vbuf = smem_base + (2 + (tile & 1)) * KV_TILE_HALF * 2;

        // ---- S = Q K^T ----
        float sacc[2][8][4];
        #pragma unroll
        for (int mt = 0; mt < 2; mt++)
            #pragma unroll
            for (int j = 0; j < 8; j++)
                #pragma unroll
                for (int c = 0; c < 4; c++) sacc[mt][j][c] = 0.f;

        #pragma unroll
        for (int kk = 0; kk < 4; kk++) {
            #pragma unroll
            for (int jp = 0; jp < 4; jp++) {
                // keys tiles 2jp, 2jp+1 ; k-chunk kk (non-trans: rows=keys)
                unsigned r0, r1, r2, r3;
                int krow = jp * 16 + ((lane >> 3) & 1) * 8 + (lane & 7);
                ldm_x4(r0, r1, r2, r3,
                       kbuf + (krow * KVST + kk * 16 + lc) * 2);
                MMA_F16(sacc[0][jp*2][0], sacc[0][jp*2][1], sacc[0][jp*2][2], sacc[0][jp*2][3],
                        qf[0][kk][0], qf[0][kk][1], qf[0][kk][2], qf[0][kk][3], r0, r2);
                MMA_F16(sacc[0][jp*2+1][0], sacc[0][jp*2+1][1], sacc[0][jp*2+1][2], sacc[0][jp*2+1][3],
                        qf[0][kk][0], qf[0][kk][1], qf[0][kk][2], qf[0][kk][3], r1, r3);
                MMA_F16(sacc[1][jp*2][0], sacc[1][jp*2][1], sacc[1][jp*2][2], sacc[1][jp*2][3],
                        qf[1][kk][0], qf[1][kk][1], qf[1][kk][2], qf[1][kk][3], r0, r2);
                MMA_F16(sacc[1][jp*2+1][0], sacc[1][jp*2+1][1], sacc[1][jp*2+1][2], sacc[1][jp*2+1][3],
                        qf[1][kk][0], qf[1][kk][1], qf[1][kk][2], qf[1][kk][3], r1, r3);
            }
        }

        // ---- online softmax + pack P to fp16 A-fragments ----
        unsigned ph[2][8][2];
        #pragma unroll
        for (int mt = 0; mt < 2; mt++) {
            float mx0 = -1e30f, mx1 = -1e30f;
            #pragma unroll
            for (int j = 0; j < 8; j++) {
                mx0 = fmaxf(mx0, fmaxf(sacc[mt][j][0], sacc[mt][j][1]));
                mx1 = fmaxf(mx1, fmaxf(sacc[mt][j][2], sacc[mt][j][3]));
            }
            mx0 = fmaxf(mx0, __shfl_xor_sync(0xffffffffu, mx0, 1));
            mx0 = fmaxf(mx0, __shfl_xor_sync(0xffffffffu, mx0, 2));
            mx1 = fmaxf(mx1, __shfl_xor_sync(0xffffffffu, mx1, 1));
            mx1 = fmaxf(mx1, __shfl_xor_sync(0xffffffffu, mx1, 2));

            float mn0 = fmaxf(mrow[mt][0], mx0);
            float mn1 = fmaxf(mrow[mt][1], mx1);
            float corr0 = __expf(mrow[mt][0] - mn0);
            float corr1 = __expf(mrow[mt][1] - mn1);
            mrow[mt][0] = mn0; mrow[mt][1] = mn1;

            float sum0 = 0.f, sum1 = 0.f;
            #pragma unroll
            for (int j = 0; j < 8; j++) {
                float p0 = __expf(sacc[mt][j][0] - mn0);
                float p1 = __expf(sacc[mt][j][1] - mn0);
                float p2 = __expf(sacc[mt][j][2] - mn1);
                float p3 = __expf(sacc[mt][j][3] - mn1);
                sum0 += p0 + p1;
                sum1 += p2 + p3;
                ph[mt][j][0] = packh2(p0, p1);
                ph[mt][j][1] = packh2(p2, p3);
            }
            sum0 += __shfl_xor_sync(0xffffffffu, sum0, 1);
            sum0 += __shfl_xor_sync(0xffffffffu, sum0, 2);
            sum1 += __shfl_xor_sync(0xffffffffu, sum1, 1);
            sum1 += __shfl_xor_sync(0xffffffffu, sum1, 2);
            lrow[mt][0] = lrow[mt][0] * corr0 + sum0;
            lrow[mt][1] = lrow[mt][1] * corr1 + sum1;

            #pragma unroll
            for (int j = 0; j < 8; j++) {
                of[mt][j][0] *= corr0; of[mt][j][1] *= corr0;
                of[mt][j][2] *= corr1; of[mt][j][3] *= corr1;
            }
        }

        // ---- O += P V ----
        #pragma unroll
        for (int kk = 0; kk < 4; kk++) {
            #pragma unroll
            for (int jp = 0; jp < 4; jp++) {
                // V rows = keys 16kk..+15, cols d-tiles 2jp, 2jp+1 (trans)
                unsigned r0, r1, r2, r3;
                ldm_x4_t(r0, r1, r2, r3,
                         vbuf + ((kk * 16 + lr) * KVST + jp * 16 + lc) * 2);
                #pragma unroll
                for (int mt = 0; mt < 2; mt++) {
                    MMA_F16(of[mt][jp*2][0], of[mt][jp*2][1], of[mt][jp*2][2], of[mt][jp*2][3],
                            ph[mt][kk*2][0], ph[mt][kk*2][1],
                            ph[mt][kk*2+1][0], ph[mt][kk*2+1][1], r0, r1);
                    MMA_F16(of[mt][jp*2+1][0], of[mt][jp*2+1][1], of[mt][jp*2+1][2], of[mt][jp*2+1][3],
                            ph[mt][kk*2][0], ph[mt][kk*2][1],
                            ph[mt][kk*2+1][0], ph[mt][kk*2+1][1], r2, r3);
                }
            }
        }
        __syncthreads();
    }

    // ---- epilogue: normalize, write fp16 to [b*n, h*64+d] ----
    const int b = bh >> 4, h = bh & 15;
    #pragma unroll
    for (int mt = 0; mt < 2; mt++) {
        float inv0 = 1.0f / lrow[mt][0];
        float inv1 = 1.0f / lrow[mt][1];
        size_t row0 = ((size_t)b * N_ + qbase + mt * 16 + g) * D_ + h * HD_;
        size_t row1 = row0 + (size_t)8 * D_;
        #pragma unroll
        for (int j = 0; j < 8; j++) {
            int d = j * 8 + t * 2;
            __half2 v0 = __floats2half2_rn(of[mt][j][0] * inv0, of[mt][j][1] * inv0);
            __half2 v1 = __floats2half2_rn(of[mt][j][2] * inv1, of[mt][j][3] * inv1);
            *(__half2*)&g_oh[row0 + d] = v0;
            *(__half2*)&g_oh[row1 + d] = v1;
        }
    }
}

// ---------------- launch --------------------------------------------------------
extern "C" void kernel_launch(void* const* d_in, const int* in_sizes, int n_in,
                              void* d_out, int out_size)
{
    const float* x       = (const float*)d_in[0];
    const float* Wqkv    = (const float*)d_in[1];
    const float* bqkv    = (const float*)d_in[2];
    const float* Wout    = (const float*)d_in[3];
    const float* bout    = (const float*)d_in[4];
    const float* q_scale = (const float*)d_in[5];
    const float* k_scale = (const float*)d_in[6];
    float* out = (float*)d_out;

    float *qkv_p = nullptr;
    __half *xh_p, *wqkvh_p, *wouth_p, *oh_p;
    cudaGetSymbolAddress((void**)&qkv_p,   g_qkv);
    cudaGetSymbolAddress((void**)&xh_p,    g_xh);
    cudaGetSymbolAddress((void**)&wqkvh_p, g_wqkvh);
    cudaGetSymbolAddress((void**)&wouth_p, g_wouth);
    cudaGetSymbolAddress((void**)&oh_p,    g_oh);

    cudaFuncSetAttribute(gemm_f16_bias,
                         cudaFuncAttributeMaxDynamicSharedMemorySize, GEMM_SMEM_BYTES);
    cudaFuncSetAttribute(attn_f16_kernel,
                         cudaFuncAttributeMaxDynamicSharedMemorySize, ATTN_SMEM_BYTES);

    // 0. fp16 conversions + RoPE tables
    f2h_kernel<<<(M_ * D_ / 4 + 255) / 256, 256>>>(x, xh_p, M_ * D_ / 4);
    f2h_kernel<<<(D_ * N3_ / 4 + 255) / 256, 256>>>(Wqkv, wqkvh_p, D_ * N3_ / 4);
    f2h_kernel<<<(D_ * D_ / 4 + 255) / 256, 256>>>(Wout, wouth_p, D_ * D_ / 4);
    rope_tables_kernel<<<(N_ * 32 + 255) / 256, 256>>>();

    // 1. QKV GEMM (fp16 in, fp32 out)
    dim3 g1(N3_ / GBN, M_ / GBM);
    gemm_f16_bias<<<g1, 256, GEMM_SMEM_BYTES>>>(xh_p, wqkvh_p, bqkv, qkv_p, M_, N3_, D_);

    // 2. RMSNorm + RoPE + reshape (writes fp16 q/k/v, q pre-scaled)
    rmsnorm_rope_kernel<<<(B_ * N_ * H_) / 8, 256>>>(q_scale, k_scale);

    // 3. Flash attention (fp16 mma)
    attn_f16_kernel<<<dim3(N_ / 128, B_ * H_), 128, ATTN_SMEM_BYTES>>>();

    // 4. Output GEMM
    dim3 g2(D_ / GBN, M_ / GBM);
    gemm_f16_bias<<<g2, 256, GEMM_SMEM_BYTES>>>(oh_p, wouth_p, bout, out, M_, D_, D_);
}

// round 6
// speedup vs baseline: 6.9718x; 1.1046x over previous
#include <cuda_runtime.h>
#include <cuda_fp16.h>
#include <math.h>

#define B_  8
#define N_  1024
#define D_  1024
#define H_  16
#define HD_ 64
#define M_  (B_ * N_)
#define N3_ (3 * D_)

// ---------------- scratch ----------------------------------------------------
__device__ __half g_xh [(size_t)M_ * D_];             // fp16 x
__device__ __half g_wqkvh[(size_t)D_ * N3_];          // fp16 Wqkv
__device__ __half g_wouth[(size_t)D_ * D_];           // fp16 Wout
__device__ __half g_qh [(size_t)B_ * H_ * N_ * HD_];  // fp16 q (pre-scaled)
__device__ __half g_kh [(size_t)B_ * H_ * N_ * HD_];
__device__ __half g_vh [(size_t)B_ * H_ * N_ * HD_];
__device__ __half g_oh [(size_t)M_ * D_];             // fp16 attention out
__device__ float  g_cos[N_ * 32];
__device__ float  g_sin[N_ * 32];

// ---------------- helpers -----------------------------------------------------
#define MMA_F16(d0,d1,d2,d3,a0,a1,a2,a3,b0,b1)                            \
    asm volatile(                                                          \
        "mma.sync.aligned.m16n8k16.row.col.f32.f16.f16.f32 "               \
        "{%0,%1,%2,%3},{%4,%5,%6,%7},{%8,%9},{%0,%1,%2,%3};\n"             \
        : "+f"(d0), "+f"(d1), "+f"(d2), "+f"(d3)                           \
        : "r"(a0), "r"(a1), "r"(a2), "r"(a3), "r"(b0), "r"(b1))

__device__ __forceinline__ void ldm_x4(unsigned& r0, unsigned& r1,
                                       unsigned& r2, unsigned& r3, unsigned a) {
    asm volatile("ldmatrix.sync.aligned.m8n8.x4.shared.b16 {%0,%1,%2,%3}, [%4];\n"
                 : "=r"(r0), "=r"(r1), "=r"(r2), "=r"(r3) : "r"(a));
}
__device__ __forceinline__ void ldm_x4_t(unsigned& r0, unsigned& r1,
                                         unsigned& r2, unsigned& r3, unsigned a) {
    asm volatile("ldmatrix.sync.aligned.m8n8.x4.trans.shared.b16 {%0,%1,%2,%3}, [%4];\n"
                 : "=r"(r0), "=r"(r1), "=r"(r2), "=r"(r3) : "r"(a));
}
__device__ __forceinline__ void cp16(unsigned smem_addr, const void* gptr) {
    asm volatile("cp.async.cg.shared.global [%0], [%1], 16;\n"
                 :: "r"(smem_addr), "l"(gptr));
}
#define CP_COMMIT() asm volatile("cp.async.commit_group;\n")
#define CP_WAIT(n)  asm volatile("cp.async.wait_group %0;\n" :: "n"(n))

__device__ __forceinline__ unsigned packh2(float a, float b) {
    __half2 h = __floats2half2_rn(a, b);
    return *(unsigned*)&h;
}

// ---------------- fp32 -> fp16 conversion -------------------------------------
__global__ void f2h_kernel(const float* __restrict__ src, __half* __restrict__ dst,
                           int n4) {
    int i = blockIdx.x * blockDim.x + threadIdx.x;
    if (i >= n4) return;
    float4 v = ((const float4*)src)[i];
    ((__half2*)dst)[i * 2]     = __floats2half2_rn(v.x, v.y);
    ((__half2*)dst)[i * 2 + 1] = __floats2half2_rn(v.z, v.w);
}

// ---------------- RoPE tables (fp32 math) --------------------------------------
__global__ void rope_tables_kernel() {
    int i = blockIdx.x * blockDim.x + threadIdx.x;
    if (i >= N_ * 32) return;
    int n = i >> 5, j = i & 31;
    int pos = (j < 16) ? (n >> 5) : (n & 31);
    int jj  = (j < 16) ? j : (j - 16);
    // 10000^(-jj/16) = exp2(-jj * log2(10000)/16)
    float invf = exp2f(-(float)jj * (13.287712379549449f / 16.0f));
    float ang  = (float)pos * invf;
    g_cos[i] = cosf(ang);
    g_sin[i] = sinf(ang);
}

// ====================== fp16 tensor-core GEMM core =============================
// Block 128x256x32, 8 warps (2x4), warp tile 64x64, cp.async 3-stage, ldmatrix.
// FUSED=0: C(fp32) = A@B + bias.
// FUSED=1: QKV epilogue — bias + RMSNorm + RoPE + reshape, writes g_qh/g_kh/g_vh.
#define GBM 128
#define GBN 256
#define GBK 32
#define AST 40
#define BST 264
#define A_HALF (GBM * AST)
#define B_HALF (GBK * BST)
#define STG_HALF (A_HALF + B_HALF)
#define NSTAGE 3
#define GEMM_SMEM_BYTES (NSTAGE * STG_HALF * 2)

template<int FUSED>
__global__ __launch_bounds__(256, 1)
void gemm_f16_core(const __half* __restrict__ A, const __half* __restrict__ Bm,
                   const float* __restrict__ bias, float* __restrict__ C,
                   const float* __restrict__ q_scale,
                   const float* __restrict__ k_scale,
                   int M, int N, int K)
{
    extern __shared__ __half sm[];
    const unsigned smem_base = (unsigned)__cvta_generic_to_shared(sm);

    const int tid  = threadIdx.x;
    const int warp = tid >> 5;
    const int lane = tid & 31;
    const int wm   = warp & 1;
    const int wn   = warp >> 1;
    const int g    = lane >> 2;
    const int t    = lane & 3;
    const int brow = blockIdx.y * GBM;
    const int bcol = blockIdx.x * GBN;

    float acc[4][8][4];
    #pragma unroll
    for (int i = 0; i < 4; i++)
        #pragma unroll
        for (int j = 0; j < 8; j++)
            #pragma unroll
            for (int c = 0; c < 4; c++) acc[i][j][c] = 0.f;

    const int T = K / GBK;

    auto issue = [&](int s, int k0) {
        unsigned abase = smem_base + (s * STG_HALF) * 2;
        unsigned bbase = abase + A_HALF * 2;
        #pragma unroll
        for (int it = 0; it < 2; it++) {
            int idx = tid + it * 256;
            int row = idx >> 2, cc = (idx & 3) * 8;
            cp16(abase + (row * AST + cc) * 2,
                 &A[(size_t)(brow + row) * K + k0 + cc]);
        }
        #pragma unroll
        for (int it = 0; it < 4; it++) {
            int idx = tid + it * 256;
            int row = idx >> 5, cc = (idx & 31) * 8;
            cp16(bbase + (row * BST + cc) * 2,
                 &Bm[(size_t)(k0 + row) * N + bcol + cc]);
        }
    };

    issue(0, 0);     CP_COMMIT();
    issue(1, GBK);   CP_COMMIT();

    const int a_r = (lane & 15);
    const int a_c = (lane >> 4) * 8;
    int sc_ = 0;
    for (int ti = 0; ti < T; ti++) {
        CP_WAIT(1);
        __syncthreads();
        if (ti + 2 < T) issue((sc_ + 2) % NSTAGE, (ti + 2) * GBK);
        CP_COMMIT();

        unsigned abase = smem_base + (sc_ * STG_HALF) * 2;
        unsigned bbase = abase + A_HALF * 2;

        #pragma unroll
        for (int ks = 0; ks < 2; ks++) {
            const int kb = ks * 16;
            unsigned af[4][4], bf[8][2];
            #pragma unroll
            for (int i = 0; i < 4; i++) {
                int m0 = wm * 64 + i * 16;
                ldm_x4(af[i][0], af[i][1], af[i][2], af[i][3],
                       abase + ((m0 + a_r) * AST + kb + a_c) * 2);
            }
            #pragma unroll
            for (int jp = 0; jp < 4; jp++) {
                int n0 = wn * 64 + jp * 16;
                unsigned r0, r1, r2, r3;
                ldm_x4_t(r0, r1, r2, r3,
                         bbase + ((kb + a_r) * BST + n0 + a_c) * 2);
                bf[jp * 2][0]     = r0; bf[jp * 2][1]     = r1;
                bf[jp * 2 + 1][0] = r2; bf[jp * 2 + 1][1] = r3;
            }
            #pragma unroll
            for (int i = 0; i < 4; i++)
                #pragma unroll
                for (int j = 0; j < 8; j++)
                    MMA_F16(acc[i][j][0], acc[i][j][1], acc[i][j][2], acc[i][j][3],
                            af[i][0], af[i][1], af[i][2], af[i][3],
                            bf[j][0], bf[j][1]);
        }
        sc_ = (sc_ + 1) % NSTAGE;
        __syncthreads();
    }

    // -------- epilogue --------
    // bias add (common)
    float bb[16];
    #pragma unroll
    for (int j = 0; j < 8; j++) {
        bb[j * 2]     = bias[bcol + wn * 64 + j * 8 + t * 2];
        bb[j * 2 + 1] = bias[bcol + wn * 64 + j * 8 + t * 2 + 1];
    }
    #pragma unroll
    for (int i = 0; i < 4; i++)
        #pragma unroll
        for (int j = 0; j < 8; j++) {
            acc[i][j][0] += bb[j * 2]; acc[i][j][1] += bb[j * 2 + 1];
            acc[i][j][2] += bb[j * 2]; acc[i][j][3] += bb[j * 2 + 1];
        }

    if (FUSED == 0) {
        #pragma unroll
        for (int i = 0; i < 4; i++) {
            int row = brow + wm * 64 + i * 16 + g;
            #pragma unroll
            for (int j = 0; j < 8; j++) {
                int col = bcol + wn * 64 + j * 8 + t * 2;
                float2 v0 = { acc[i][j][0], acc[i][j][1] };
                float2 v1 = { acc[i][j][2], acc[i][j][3] };
                *(float2*)&C[(size_t)row * N + col]       = v0;
                *(float2*)&C[(size_t)(row + 8) * N + col] = v1;
            }
        }
        return;
    }

    // FUSED=1: region 0=q, 1=k, 2=v ; this warp's 64 cols = one head
    const int region = blockIdx.x >> 2;
    const int h      = (blockIdx.x & 3) * 4 + wn;

    if (region == 2) {
        #pragma unroll
        for (int i = 0; i < 4; i++) {
            int grow = brow + wm * 64 + i * 16 + g;
            int nn = grow & (N_ - 1), bb_ = grow >> 10;
            size_t dst0 = ((size_t)(bb_ * H_ + h) * N_ + nn) * HD_;
            size_t dst1 = dst0 + 8 * HD_;
            #pragma unroll
            for (int j = 0; j < 8; j++) {
                int d = j * 8 + t * 2;
                *(__half2*)&g_vh[dst0 + d] = __floats2half2_rn(acc[i][j][0], acc[i][j][1]);
                *(__half2*)&g_vh[dst1 + d] = __floats2half2_rn(acc[i][j][2], acc[i][j][3]);
            }
        }
    } else {
        const float* scv = (region == 0) ? q_scale : k_scale;
        __half* outp     = (region == 0) ? g_qh : g_kh;
        const float rsmul = (region == 0) ? 0.125f : 1.0f;   // fold 1/sqrt(64) into q
        float scr[16];
        #pragma unroll
        for (int j = 0; j < 8; j++) {
            scr[j * 2]     = scv[j * 8 + t * 2];
            scr[j * 2 + 1] = scv[j * 8 + t * 2 + 1];
        }
        #pragma unroll
        for (int i = 0; i < 4; i++) {
            float ss0 = 0.f, ss1 = 0.f;
            #pragma unroll
            for (int j = 0; j < 8; j++) {
                ss0 += acc[i][j][0] * acc[i][j][0] + acc[i][j][1] * acc[i][j][1];
                ss1 += acc[i][j][2] * acc[i][j][2] + acc[i][j][3] * acc[i][j][3];
            }
            ss0 += __shfl_xor_sync(0xffffffffu, ss0, 1);
            ss0 += __shfl_xor_sync(0xffffffffu, ss0, 2);
            ss1 += __shfl_xor_sync(0xffffffffu, ss1, 1);
            ss1 += __shfl_xor_sync(0xffffffffu, ss1, 2);
            float rs0 = rsqrtf(ss0 * (1.0f / HD_) + 1e-6f) * rsmul;
            float rs1 = rsqrtf(ss1 * (1.0f / HD_) + 1e-6f) * rsmul;

            int grow = brow + wm * 64 + i * 16 + g;
            int nn = grow & (N_ - 1), bb_ = grow >> 10;
            size_t dst0 = ((size_t)(bb_ * H_ + h) * N_ + nn) * HD_;
            size_t dst1 = dst0 + 8 * HD_;
            #pragma unroll
            for (int j = 0; j < 4; j++) {
                int d = j * 8 + t * 2;
                float c00 = g_cos[nn * 32 + d],           s00 = g_sin[nn * 32 + d];
                float c01 = g_cos[nn * 32 + d + 1],       s01 = g_sin[nn * 32 + d + 1];
                float c10 = g_cos[(nn + 8) * 32 + d],     s10 = g_sin[(nn + 8) * 32 + d];
                float c11 = g_cos[(nn + 8) * 32 + d + 1], s11 = g_sin[(nn + 8) * 32 + d + 1];
                // row_lo
                float a0 = acc[i][j][0] * rs0 * scr[j * 2];
                float a1 = acc[i][j][1] * rs0 * scr[j * 2 + 1];
                float p0 = acc[i][j + 4][0] * rs0 * scr[(j + 4) * 2];
                float p1 = acc[i][j + 4][1] * rs0 * scr[(j + 4) * 2 + 1];
                *(__half2*)&outp[dst0 + d]      = __floats2half2_rn(a0 * c00 - p0 * s00, a1 * c01 - p1 * s01);
                *(__half2*)&outp[dst0 + d + 32] = __floats2half2_rn(a0 * s00 + p0 * c00, a1 * s01 + p1 * c01);
                // row_hi
                float e0 = acc[i][j][2] * rs1 * scr[j * 2];
                float e1 = acc[i][j][3] * rs1 * scr[j * 2 + 1];
                float q0 = acc[i][j + 4][2] * rs1 * scr[(j + 4) * 2];
                float q1 = acc[i][j + 4][3] * rs1 * scr[(j + 4) * 2 + 1];
                *(__half2*)&outp[dst1 + d]      = __floats2half2_rn(e0 * c10 - q0 * s10, e1 * c11 - q1 * s11);
                *(__half2*)&outp[dst1 + d + 32] = __floats2half2_rn(e0 * s10 + q0 * c10, e1 * s11 + q1 * c11);
            }
        }
    }
}

// ================ fp16 tensor-core flash attention =============================
#define KVST 72
#define KV_TILE_HALF (64 * KVST)
#define ATTN_SMEM_BYTES (4 * KV_TILE_HALF * 2)

__global__ __launch_bounds__(128)
void attn_f16_kernel()
{
    extern __shared__ __half asm_[];
    const unsigned smem_base = (unsigned)__cvta_generic_to_shared(asm_);

    const int tid  = threadIdx.x;
    const int warp = tid >> 5;
    const int lane = tid & 31;
    const int g    = lane >> 2;
    const int t    = lane & 3;
    const int bh   = blockIdx.y;
    const int qbase = blockIdx.x * 128 + warp * 32;
    const size_t base = (size_t)bh * N_ * HD_;

    unsigned qf[2][4][4];
    #pragma unroll
    for (int mt = 0; mt < 2; mt++) {
        const __half* Q0 = g_qh + base + (size_t)(qbase + mt * 16 + g) * HD_;
        const __half* Q1 = Q0 + 8 * HD_;
        #pragma unroll
        for (int kk = 0; kk < 4; kk++) {
            qf[mt][kk][0] = *(const unsigned*)&Q0[kk * 16 + 2 * t];
            qf[mt][kk][1] = *(const unsigned*)&Q1[kk * 16 + 2 * t];
            qf[mt][kk][2] = *(const unsigned*)&Q0[kk * 16 + 8 + 2 * t];
            qf[mt][kk][3] = *(const unsigned*)&Q1[kk * 16 + 8 + 2 * t];
        }
    }

    float of[2][8][4];
    #pragma unroll
    for (int mt = 0; mt < 2; mt++)
        #pragma unroll
        for (int j = 0; j < 8; j++)
            #pragma unroll
            for (int c = 0; c < 4; c++) of[mt][j][c] = 0.f;
    float mrow[2][2] = {{-1e30f, -1e30f}, {-1e30f, -1e30f}};
    float lrow[2][2] = {{0.f, 0.f}, {0.f, 0.f}};

    auto issue_tile = [&](int buf, int tile) {
        unsigned kb = smem_base + buf * KV_TILE_HALF * 2;
        unsigned vb = smem_base + (2 + buf) * KV_TILE_HALF * 2;
        const __half* kg = g_kh + base + (size_t)tile * 64 * HD_;
        const __half* vg = g_vh + base + (size_t)tile * 64 * HD_;
        #pragma unroll
        for (int it = 0; it < 4; it++) {
            int idx = tid + it * 128;
            int row = idx >> 3, cc = (idx & 7) * 8;
            cp16(kb + (row * KVST + cc) * 2, kg + row * HD_ + cc);
            cp16(vb + (row * KVST + cc) * 2, vg + row * HD_ + cc);
        }
    };

    issue_tile(0, 0);
    CP_COMMIT();

    const int lr = lane & 15;
    const int lc = (lane >> 4) * 8;

    for (int tile = 0; tile < N_ / 64; tile++) {
        if (tile + 1 < N_ / 64) issue_tile((tile + 1) & 1, tile + 1);
        CP_COMMIT();
        CP_WAIT(1);
        __syncthreads();

        unsigned kbuf = smem_base + (tile & 1) * KV_TILE_HALF * 2;
        unsigned vbuf = smem_base + (2 + (tile & 1)) * KV_TILE_HALF * 2;

        float sacc[2][8][4];
        #pragma unroll
        for (int mt = 0; mt < 2; mt++)
            #pragma unroll
            for (int j = 0; j < 8; j++)
                #pragma unroll
                for (int c = 0; c < 4; c++) sacc[mt][j][c] = 0.f;

        #pragma unroll
        for (int kk = 0; kk < 4; kk++) {
            #pragma unroll
            for (int jp = 0; jp < 4; jp++) {
                unsigned r0, r1, r2, r3;
                int krow = jp * 16 + ((lane >> 3) & 1) * 8 + (lane & 7);
                ldm_x4(r0, r1, r2, r3,
                       kbuf + (krow * KVST + kk * 16 + lc) * 2);
                MMA_F16(sacc[0][jp*2][0], sacc[0][jp*2][1], sacc[0][jp*2][2], sacc[0][jp*2][3],
                        qf[0][kk][0], qf[0][kk][1], qf[0][kk][2], qf[0][kk][3], r0, r2);
                MMA_F16(sacc[0][jp*2+1][0], sacc[0][jp*2+1][1], sacc[0][jp*2+1][2], sacc[0][jp*2+1][3],
                        qf[0][kk][0], qf[0][kk][1], qf[0][kk][2], qf[0][kk][3], r1, r3);
                MMA_F16(sacc[1][jp*2][0], sacc[1][jp*2][1], sacc[1][jp*2][2], sacc[1][jp*2][3],
                        qf[1][kk][0], qf[1][kk][1], qf[1][kk][2], qf[1][kk][3], r0, r2);
                MMA_F16(sacc[1][jp*2+1][0], sacc[1][jp*2+1][1], sacc[1][jp*2+1][2], sacc[1][jp*2+1][3],
                        qf[1][kk][0], qf[1][kk][1], qf[1][kk][2], qf[1][kk][3], r1, r3);
            }
        }

        unsigned ph[2][8][2];
        #pragma unroll
        for (int mt = 0; mt < 2; mt++) {
            float mx0 = -1e30f, mx1 = -1e30f;
            #pragma unroll
            for (int j = 0; j < 8; j++) {
                mx0 = fmaxf(mx0, fmaxf(sacc[mt][j][0], sacc[mt][j][1]));
                mx1 = fmaxf(mx1, fmaxf(sacc[mt][j][2], sacc[mt][j][3]));
            }
            mx0 = fmaxf(mx0, __shfl_xor_sync(0xffffffffu, mx0, 1));
            mx0 = fmaxf(mx0, __shfl_xor_sync(0xffffffffu, mx0, 2));
            mx1 = fmaxf(mx1, __shfl_xor_sync(0xffffffffu, mx1, 1));
            mx1 = fmaxf(mx1, __shfl_xor_sync(0xffffffffu, mx1, 2));

            float mn0 = fmaxf(mrow[mt][0], mx0);
            float mn1 = fmaxf(mrow[mt][1], mx1);
            float corr0 = __expf(mrow[mt][0] - mn0);
            float corr1 = __expf(mrow[mt][1] - mn1);
            mrow[mt][0] = mn0; mrow[mt][1] = mn1;

            float sum0 = 0.f, sum1 = 0.f;
            #pragma unroll
            for (int j = 0; j < 8; j++) {
                float p0 = __expf(sacc[mt][j][0] - mn0);
                float p1 = __expf(sacc[mt][j][1] - mn0);
                float p2 = __expf(sacc[mt][j][2] - mn1);
                float p3 = __expf(sacc[mt][j][3] - mn1);
                sum0 += p0 + p1;
                sum1 += p2 + p3;
                ph[mt][j][0] = packh2(p0, p1);
                ph[mt][j][1] = packh2(p2, p3);
            }
            sum0 += __shfl_xor_sync(0xffffffffu, sum0, 1);
            sum0 += __shfl_xor_sync(0xffffffffu, sum0, 2);
            sum1 += __shfl_xor_sync(0xffffffffu, sum1, 1);
            sum1 += __shfl_xor_sync(0xffffffffu, sum1, 2);
            lrow[mt][0] = lrow[mt][0] * corr0 + sum0;
            lrow[mt][1] = lrow[mt][1] * corr1 + sum1;

            #pragma unroll
            for (int j = 0; j < 8; j++) {
                of[mt][j][0] *= corr0; of[mt][j][1] *= corr0;
                of[mt][j][2] *= corr1; of[mt][j][3] *= corr1;
            }
        }

        #pragma unroll
        for (int kk = 0; kk < 4; kk++) {
            #pragma unroll
            for (int jp = 0; jp < 4; jp++) {
                unsigned r0, r1, r2, r3;
                ldm_x4_t(r0, r1, r2, r3,
                         vbuf + ((kk * 16 + lr) * KVST + jp * 16 + lc) * 2);
                #pragma unroll
                for (int mt = 0; mt < 2; mt++) {
                    MMA_F16(of[mt][jp*2][0], of[mt][jp*2][1], of[mt][jp*2][2], of[mt][jp*2][3],
                            ph[mt][kk*2][0], ph[mt][kk*2][1],
                            ph[mt][kk*2+1][0], ph[mt][kk*2+1][1], r0, r1);
                    MMA_F16(of[mt][jp*2+1][0], of[mt][jp*2+1][1], of[mt][jp*2+1][2], of[mt][jp*2+1][3],
                            ph[mt][kk*2][0], ph[mt][kk*2][1],
                            ph[mt][kk*2+1][0], ph[mt][kk*2+1][1], r2, r3);
                }
            }
        }
        __syncthreads();
    }

    const int b = bh >> 4, h = bh & 15;
    #pragma unroll
    for (int mt = 0; mt < 2; mt++) {
        float inv0 = 1.0f / lrow[mt][0];
        float inv1 = 1.0f / lrow[mt][1];
        size_t row0 = ((size_t)b * N_ + qbase + mt * 16 + g) * D_ + h * HD_;
        size_t row1 = row0 + (size_t)8 * D_;
        #pragma unroll
        for (int j = 0; j < 8; j++) {
            int d = j * 8 + t * 2;
            __half2 v0 = __floats2half2_rn(of[mt][j][0] * inv0, of[mt][j][1] * inv0);
            __half2 v1 = __floats2half2_rn(of[mt][j][2] * inv1, of[mt][j][3] * inv1);
            *(__half2*)&g_oh[row0 + d] = v0;
            *(__half2*)&g_oh[row1 + d] = v1;
        }
    }
}

// ---------------- launch --------------------------------------------------------
extern "C" void kernel_launch(void* const* d_in, const int* in_sizes, int n_in,
                              void* d_out, int out_size)
{
    const float* x       = (const float*)d_in[0];
    const float* Wqkv    = (const float*)d_in[1];
    const float* bqkv    = (const float*)d_in[2];
    const float* Wout    = (const float*)d_in[3];
    const float* bout    = (const float*)d_in[4];
    const float* q_scale = (const float*)d_in[5];
    const float* k_scale = (const float*)d_in[6];
    float* out = (float*)d_out;

    __half *xh_p, *wqkvh_p, *wouth_p, *oh_p;
    cudaGetSymbolAddress((void**)&xh_p,    g_xh);
    cudaGetSymbolAddress((void**)&wqkvh_p, g_wqkvh);
    cudaGetSymbolAddress((void**)&wouth_p, g_wouth);
    cudaGetSymbolAddress((void**)&oh_p,    g_oh);

    cudaFuncSetAttribute(gemm_f16_core<0>,
                         cudaFuncAttributeMaxDynamicSharedMemorySize, GEMM_SMEM_BYTES);
    cudaFuncSetAttribute(gemm_f16_core<1>,
                         cudaFuncAttributeMaxDynamicSharedMemorySize, GEMM_SMEM_BYTES);
    cudaFuncSetAttribute(attn_f16_kernel,
                         cudaFuncAttributeMaxDynamicSharedMemorySize, ATTN_SMEM_BYTES);

    // 0. fp16 conversions + RoPE tables
    f2h_kernel<<<(M_ * D_ / 4 + 255) / 256, 256>>>(x, xh_p, M_ * D_ / 4);
    f2h_kernel<<<(D_ * N3_ / 4 + 255) / 256, 256>>>(Wqkv, wqkvh_p, D_ * N3_ / 4);
    f2h_kernel<<<(D_ * D_ / 4 + 255) / 256, 256>>>(Wout, wouth_p, D_ * D_ / 4);
    rope_tables_kernel<<<(N_ * 32 + 255) / 256, 256>>>();

    // 1. QKV GEMM with fused bias+RMSNorm+RoPE+reshape -> g_qh/g_kh/g_vh
    dim3 g1(N3_ / GBN, M_ / GBM);
    gemm_f16_core<1><<<g1, 256, GEMM_SMEM_BYTES>>>(
        xh_p, wqkvh_p, bqkv, nullptr, q_scale, k_scale, M_, N3_, D_);

    // 2. Flash attention (fp16 mma)
    attn_f16_kernel<<<dim3(N_ / 128, B_ * H_), 128, ATTN_SMEM_BYTES>>>();

    // 3. Output GEMM
    dim3 g2(D_ / GBN, M_ / GBM);
    gemm_f16_core<0><<<g2, 256, GEMM_SMEM_BYTES>>>(
        oh_p, wouth_p, bout, out, nullptr, nullptr, M_, D_, D_);
}

// round 8
// speedup vs baseline: 7.1488x; 1.0254x over previous
#include <cuda_runtime.h>
#include <cuda_fp16.h>
#include <math.h>

#define B_  8
#define N_  1024
#define D_  1024
#define H_  16
#define HD_ 64
#define M_  (B_ * N_)
#define N3_ (3 * D_)

// ---------------- scratch ----------------------------------------------------
__device__ __half g_xh [(size_t)M_ * D_];             // fp16 x
__device__ __half g_wqkvh[(size_t)D_ * N3_];          // fp16 Wqkv
__device__ __half g_wouth[(size_t)D_ * D_];           // fp16 Wout
__device__ __half g_qh [(size_t)B_ * H_ * N_ * HD_];  // fp16 q (pre-scaled)
__device__ __half g_kh [(size_t)B_ * H_ * N_ * HD_];
__device__ __half g_vh [(size_t)B_ * H_ * N_ * HD_];
__device__ __half g_oh [(size_t)M_ * D_];             // fp16 attention out
__device__ float  g_cos[N_ * 32];
__device__ float  g_sin[N_ * 32];

// ---------------- helpers -----------------------------------------------------
#define MMA_F16(d0,d1,d2,d3,a0,a1,a2,a3,b0,b1)                            \
    asm volatile(                                                          \
        "mma.sync.aligned.m16n8k16.row.col.f32.f16.f16.f32 "               \
        "{%0,%1,%2,%3},{%4,%5,%6,%7},{%8,%9},{%0,%1,%2,%3};\n"             \
        : "+f"(d0), "+f"(d1), "+f"(d2), "+f"(d3)                           \
        : "r"(a0), "r"(a1), "r"(a2), "r"(a3), "r"(b0), "r"(b1))

__device__ __forceinline__ void ldm_x4(unsigned& r0, unsigned& r1,
                                       unsigned& r2, unsigned& r3, unsigned a) {
    asm volatile("ldmatrix.sync.aligned.m8n8.x4.shared.b16 {%0,%1,%2,%3}, [%4];\n"
                 : "=r"(r0), "=r"(r1), "=r"(r2), "=r"(r3) : "r"(a));
}
__device__ __forceinline__ void ldm_x4_t(unsigned& r0, unsigned& r1,
                                         unsigned& r2, unsigned& r3, unsigned a) {
    asm volatile("ldmatrix.sync.aligned.m8n8.x4.trans.shared.b16 {%0,%1,%2,%3}, [%4];\n"
                 : "=r"(r0), "=r"(r1), "=r"(r2), "=r"(r3) : "r"(a));
}
__device__ __forceinline__ void cp16(unsigned smem_addr, const void* gptr) {
    asm volatile("cp.async.cg.shared.global [%0], [%1], 16;\n"
                 :: "r"(smem_addr), "l"(gptr));
}
#define CP_COMMIT() asm volatile("cp.async.commit_group;\n")
#define CP_WAIT(n)  asm volatile("cp.async.wait_group %0;\n" :: "n"(n))

__device__ __forceinline__ unsigned packh2(float a, float b) {
    __half2 h = __floats2half2_rn(a, b);
    return *(unsigned*)&h;
}

// ---------------- fused fp32 -> fp16 conversion (x, Wqkv, Wout) ----------------
#define X4_  (M_ * D_ / 4)
#define W14_ (D_ * N3_ / 4)
#define W24_ (D_ * D_ / 4)
__global__ void f2h_all_kernel(const float* __restrict__ x,
                               const float* __restrict__ w1,
                               const float* __restrict__ w2) {
    int i = blockIdx.x * blockDim.x + threadIdx.x;
    const float* src;
    __half* dst;
    int off;
    if (i < X4_) {
        src = x;  dst = g_xh;    off = i;
    } else if (i < X4_ + W14_) {
        src = w1; dst = g_wqkvh; off = i - X4_;
    } else if (i < X4_ + W14_ + W24_) {
        src = w2; dst = g_wouth; off = i - X4_ - W14_;
    } else return;
    float4 v = ((const float4*)src)[off];
    ((__half2*)dst)[off * 2]     = __floats2half2_rn(v.x, v.y);
    ((__half2*)dst)[off * 2 + 1] = __floats2half2_rn(v.z, v.w);
}

// ---------------- RoPE tables ---------------------------------------------------
__global__ void rope_tables_kernel() {
    int i = blockIdx.x * blockDim.x + threadIdx.x;
    if (i >= N_ * 32) return;
    int n = i >> 5, j = i & 31;
    int pos = (j < 16) ? (n >> 5) : (n & 31);
    int jj  = (j < 16) ? j : (j - 16);
    float invf = exp2f(-(float)jj * (13.287712379549449f / 16.0f));
    float ang  = (float)pos * invf;
    g_cos[i] = cosf(ang);
    g_sin[i] = sinf(ang);
}

// ====================== fp16 tensor-core GEMM + epilogues (R6) ==================
#define GBM 128
#define GBN 256
#define GBK 32
#define AST 40
#define BST 264
#define A_HALF (GBM * AST)
#define B_HALF (GBK * BST)
#define STG_HALF (A_HALF + B_HALF)
#define NSTAGE 3
#define GEMM_SMEM_BYTES (NSTAGE * STG_HALF * 2)

template<int FUSED>
__global__ __launch_bounds__(256, 1)
void gemm_f16_core(const __half* __restrict__ A, const __half* __restrict__ Bm,
                   const float* __restrict__ bias, float* __restrict__ C,
                   const float* __restrict__ q_scale,
                   const float* __restrict__ k_scale,
                   int M, int N, int K)
{
    extern __shared__ __half sm[];
    const unsigned smem_base = (unsigned)__cvta_generic_to_shared(sm);

    const int tid  = threadIdx.x;
    const int warp = tid >> 5;
    const int lane = tid & 31;
    const int wm   = warp & 1;
    const int wn   = warp >> 1;
    const int g    = lane >> 2;
    const int t    = lane & 3;
    const int brow = blockIdx.y * GBM;
    const int bcol = blockIdx.x * GBN;

    float acc[4][8][4];
    #pragma unroll
    for (int i = 0; i < 4; i++)
        #pragma unroll
        for (int j = 0; j < 8; j++)
            #pragma unroll
            for (int c = 0; c < 4; c++) acc[i][j][c] = 0.f;

    const int T = K / GBK;

    auto issue = [&](int s, int k0) {
        unsigned abase = smem_base + (s * STG_HALF) * 2;
        unsigned bbase = abase + A_HALF * 2;
        #pragma unroll
        for (int it = 0; it < 2; it++) {
            int idx = tid + it * 256;
            int row = idx >> 2, cc = (idx & 3) * 8;
            cp16(abase + (row * AST + cc) * 2,
                 &A[(size_t)(brow + row) * K + k0 + cc]);
        }
        #pragma unroll
        for (int it = 0; it < 4; it++) {
            int idx = tid + it * 256;
            int row = idx >> 5, cc = (idx & 31) * 8;
            cp16(bbase + (row * BST + cc) * 2,
                 &Bm[(size_t)(k0 + row) * N + bcol + cc]);
        }
    };

    issue(0, 0);     CP_COMMIT();
    issue(1, GBK);   CP_COMMIT();

    const int a_r = (lane & 15);
    const int a_c = (lane >> 4) * 8;
    int sc_ = 0;
    for (int ti = 0; ti < T; ti++) {
        CP_WAIT(1);
        __syncthreads();
        if (ti + 2 < T) issue((sc_ + 2) % NSTAGE, (ti + 2) * GBK);
        CP_COMMIT();

        unsigned abase = smem_base + (sc_ * STG_HALF) * 2;
        unsigned bbase = abase + A_HALF * 2;

        #pragma unroll
        for (int ks = 0; ks < 2; ks++) {
            const int kb = ks * 16;
            unsigned af[4][4], bf[8][2];
            #pragma unroll
            for (int i = 0; i < 4; i++) {
                int m0 = wm * 64 + i * 16;
                ldm_x4(af[i][0], af[i][1], af[i][2], af[i][3],
                       abase + ((m0 + a_r) * AST + kb + a_c) * 2);
            }
            #pragma unroll
            for (int jp = 0; jp < 4; jp++) {
                int n0 = wn * 64 + jp * 16;
                unsigned r0, r1, r2, r3;
                ldm_x4_t(r0, r1, r2, r3,
                         bbase + ((kb + a_r) * BST + n0 + a_c) * 2);
                bf[jp * 2][0]     = r0; bf[jp * 2][1]     = r1;
                bf[jp * 2 + 1][0] = r2; bf[jp * 2 + 1][1] = r3;
            }
            #pragma unroll
            for (int i = 0; i < 4; i++)
                #pragma unroll
                for (int j = 0; j < 8; j++)
                    MMA_F16(acc[i][j][0], acc[i][j][1], acc[i][j][2], acc[i][j][3],
                            af[i][0], af[i][1], af[i][2], af[i][3],
                            bf[j][0], bf[j][1]);
        }
        sc_ = (sc_ + 1) % NSTAGE;
        __syncthreads();
    }

    float bb[16];
    #pragma unroll
    for (int j = 0; j < 8; j++) {
        bb[j * 2]     = bias[bcol + wn * 64 + j * 8 + t * 2];
        bb[j * 2 + 1] = bias[bcol + wn * 64 + j * 8 + t * 2 + 1];
    }
    #pragma unroll
    for (int i = 0; i < 4; i++)
        #pragma unroll
        for (int j = 0; j < 8; j++) {
            acc[i][j][0] += bb[j * 2]; acc[i][j][1] += bb[j * 2 + 1];
            acc[i][j][2] += bb[j * 2]; acc[i][j][3] += bb[j * 2 + 1];
        }

    if (FUSED == 0) {
        #pragma unroll
        for (int i = 0; i < 4; i++) {
            int row = brow + wm * 64 + i * 16 + g;
            #pragma unroll
            for (int j = 0; j < 8; j++) {
                int col = bcol + wn * 64 + j * 8 + t * 2;
                float2 v0 = { acc[i][j][0], acc[i][j][1] };
                float2 v1 = { acc[i][j][2], acc[i][j][3] };
                *(float2*)&C[(size_t)row * N + col]       = v0;
                *(float2*)&C[(size_t)(row + 8) * N + col] = v1;
            }
        }
        return;
    }

    const int region = blockIdx.x >> 2;
    const int h      = (blockIdx.x & 3) * 4 + wn;

    if (region == 2) {
        #pragma unroll
        for (int i = 0; i < 4; i++) {
            int grow = brow + wm * 64 + i * 16 + g;
            int nn = grow & (N_ - 1), bb_ = grow >> 10;
            size_t dst0 = ((size_t)(bb_ * H_ + h) * N_ + nn) * HD_;
            size_t dst1 = dst0 + 8 * HD_;
            #pragma unroll
            for (int j = 0; j < 8; j++) {
                int d = j * 8 + t * 2;
                *(__half2*)&g_vh[dst0 + d] = __floats2half2_rn(acc[i][j][0], acc[i][j][1]);
                *(__half2*)&g_vh[dst1 + d] = __floats2half2_rn(acc[i][j][2], acc[i][j][3]);
            }
        }
    } else {
        const float* scv = (region == 0) ? q_scale : k_scale;
        __half* outp     = (region == 0) ? g_qh : g_kh;
        const float rsmul = (region == 0) ? 0.125f : 1.0f;
        float scr[16];
        #pragma unroll
        for (int j = 0; j < 8; j++) {
            scr[j * 2]     = scv[j * 8 + t * 2];
            scr[j * 2 + 1] = scv[j * 8 + t * 2 + 1];
        }
        #pragma unroll
        for (int i = 0; i < 4; i++) {
            float ss0 = 0.f, ss1 = 0.f;
            #pragma unroll
            for (int j = 0; j < 8; j++) {
                ss0 += acc[i][j][0] * acc[i][j][0] + acc[i][j][1] * acc[i][j][1];
                ss1 += acc[i][j][2] * acc[i][j][2] + acc[i][j][3] * acc[i][j][3];
            }
            ss0 += __shfl_xor_sync(0xffffffffu, ss0, 1);
            ss0 += __shfl_xor_sync(0xffffffffu, ss0, 2);
            ss1 += __shfl_xor_sync(0xffffffffu, ss1, 1);
            ss1 += __shfl_xor_sync(0xffffffffu, ss1, 2);
            float rs0 = rsqrtf(ss0 * (1.0f / HD_) + 1e-6f) * rsmul;
            float rs1 = rsqrtf(ss1 * (1.0f / HD_) + 1e-6f) * rsmul;

            int grow = brow + wm * 64 + i * 16 + g;
            int nn = grow & (N_ - 1), bb_ = grow >> 10;
            size_t dst0 = ((size_t)(bb_ * H_ + h) * N_ + nn) * HD_;
            size_t dst1 = dst0 + 8 * HD_;
            #pragma unroll
            for (int j = 0; j < 4; j++) {
                int d = j * 8 + t * 2;
                float c00 = g_cos[nn * 32 + d],           s00 = g_sin[nn * 32 + d];
                float c01 = g_cos[nn * 32 + d + 1],       s01 = g_sin[nn * 32 + d + 1];
                float c10 = g_cos[(nn + 8) * 32 + d],     s10 = g_sin[(nn + 8) * 32 + d];
                float c11 = g_cos[(nn + 8) * 32 + d + 1], s11 = g_sin[(nn + 8) * 32 + d + 1];
                float a0 = acc[i][j][0] * rs0 * scr[j * 2];
                float a1 = acc[i][j][1] * rs0 * scr[j * 2 + 1];
                float p0 = acc[i][j + 4][0] * rs0 * scr[(j + 4) * 2];
                float p1 = acc[i][j + 4][1] * rs0 * scr[(j + 4) * 2 + 1];
                *(__half2*)&outp[dst0 + d]      = __floats2half2_rn(a0 * c00 - p0 * s00, a1 * c01 - p1 * s01);
                *(__half2*)&outp[dst0 + d + 32] = __floats2half2_rn(a0 * s00 + p0 * c00, a1 * s01 + p1 * c01);
                float e0 = acc[i][j][2] * rs1 * scr[j * 2];
                float e1 = acc[i][j][3] * rs1 * scr[j * 2 + 1];
                float q0 = acc[i][j + 4][2] * rs1 * scr[(j + 4) * 2];
                float q1 = acc[i][j + 4][3] * rs1 * scr[(j + 4) * 2 + 1];
                *(__half2*)&outp[dst1 + d]      = __floats2half2_rn(e0 * c10 - q0 * s10, e1 * c11 - q1 * s11);
                *(__half2*)&outp[dst1 + d + 32] = __floats2half2_rn(e0 * s10 + q0 * c10, e1 * s11 + q1 * c11);
            }
        }
    }
}

// ================ fp16 flash attention: f16x2 exp + ones-column l ===============
#define KVST 88   // stride in halves; 48*r mod 128 cycles all banks -> conflict-free
#define KV_TILE_HALF (64 * KVST)
#define ATTN_SMEM_BYTES (4 * KV_TILE_HALF * 2)   // 45056

__global__ __launch_bounds__(128)
void attn_f16_kernel()
{
    extern __shared__ __half asm_[];
    const unsigned smem_base = (unsigned)__cvta_generic_to_shared(asm_);

    const int tid  = threadIdx.x;
    const int warp = tid >> 5;
    const int lane = tid & 31;
    const int g    = lane >> 2;
    const int t    = lane & 3;
    const int bh   = blockIdx.y;
    const int qbase = blockIdx.x * 128 + warp * 32;
    const size_t base = (size_t)bh * N_ * HD_;
    const float LOG2E = 1.44269504f;

    // init V pad columns 64..71 (col 64 = 1.0 -> accumulates row sum of P)
    {
        int buf = tid >> 6, row = tid & 63;
        __half* p = asm_ + (size_t)(2 + buf) * KV_TILE_HALF + row * KVST + 64;
        p[0] = __float2half(1.0f);
        #pragma unroll
        for (int j = 1; j < 8; j++) p[j] = __float2half(0.0f);
    }

    unsigned qf[2][4][4];
    #pragma unroll
    for (int mt = 0; mt < 2; mt++) {
        const __half* Q0 = g_qh + base + (size_t)(qbase + mt * 16 + g) * HD_;
        const __half* Q1 = Q0 + 8 * HD_;
        #pragma unroll
        for (int kk = 0; kk < 4; kk++) {
            qf[mt][kk][0] = *(const unsigned*)&Q0[kk * 16 + 2 * t];
            qf[mt][kk][1] = *(const unsigned*)&Q1[kk * 16 + 2 * t];
            qf[mt][kk][2] = *(const unsigned*)&Q0[kk * 16 + 8 + 2 * t];
            qf[mt][kk][3] = *(const unsigned*)&Q1[kk * 16 + 8 + 2 * t];
        }
    }

    float of[2][8][4];
    float ofl[2][4];   // ones-column accumulator: col 64 = row-sum l
    #pragma unroll
    for (int mt = 0; mt < 2; mt++) {
        #pragma unroll
        for (int j = 0; j < 8; j++)
            #pragma unroll
            for (int c = 0; c < 4; c++) of[mt][j][c] = 0.f;
        #pragma unroll
        for (int c = 0; c < 4; c++) ofl[mt][c] = 0.f;
    }
    float mrow[2][2] = {{-1e30f, -1e30f}, {-1e30f, -1e30f}};

    auto issue_tile = [&](int buf, int tile) {
        unsigned kb = smem_base + buf * KV_TILE_HALF * 2;
        unsigned vb = smem_base + (2 + buf) * KV_TILE_HALF * 2;
        const __half* kg = g_kh + base + (size_t)tile * 64 * HD_;
        const __half* vg = g_vh + base + (size_t)tile * 64 * HD_;
        #pragma unroll
        for (int it = 0; it < 4; it++) {
            int idx = tid + it * 128;
            int row = idx >> 3, cc = (idx & 7) * 8;
            cp16(kb + (row * KVST + cc) * 2, kg + row * HD_ + cc);
            cp16(vb + (row * KVST + cc) * 2, vg + row * HD_ + cc);
        }
    };

    issue_tile(0, 0);
    CP_COMMIT();

    const int lr = lane & 15;
    const int lc = (lane >> 4) * 8;

    for (int tile = 0; tile < N_ / 64; tile++) {
        if (tile + 1 < N_ / 64) issue_tile((tile + 1) & 1, tile + 1);
        CP_COMMIT();
        CP_WAIT(1);
        __syncthreads();

        unsigned kbuf = smem_base + (tile & 1) * KV_TILE_HALF * 2;
        unsigned vbuf = smem_base + (2 + (tile & 1)) * KV_TILE_HALF * 2;

        // ---- S = Q K^T ----
        float sacc[2][8][4];
        #pragma unroll
        for (int mt = 0; mt < 2; mt++)
            #pragma unroll
            for (int j = 0; j < 8; j++)
                #pragma unroll
                for (int c = 0; c < 4; c++) sacc[mt][j][c] = 0.f;

        #pragma unroll
        for (int kk = 0; kk < 4; kk++) {
            #pragma unroll
            for (int jp = 0; jp < 4; jp++) {
                unsigned r0, r1, r2, r3;
                int krow = jp * 16 + ((lane >> 3) & 1) * 8 + (lane & 7);
                ldm_x4(r0, r1, r2, r3,
                       kbuf + (krow * KVST + kk * 16 + lc) * 2);
                MMA_F16(sacc[0][jp*2][0], sacc[0][jp*2][1], sacc[0][jp*2][2], sacc[0][jp*2][3],
                        qf[0][kk][0], qf[0][kk][1], qf[0][kk][2], qf[0][kk][3], r0, r2);
                MMA_F16(sacc[0][jp*2+1][0], sacc[0][jp*2+1][1], sacc[0][jp*2+1][2], sacc[0][jp*2+1][3],
                        qf[0][kk][0], qf[0][kk][1], qf[0][kk][2], qf[0][kk][3], r1, r3);
                MMA_F16(sacc[1][jp*2][0], sacc[1][jp*2][1], sacc[1][jp*2][2], sacc[1][jp*2][3],
                        qf[1][kk][0], qf[1][kk][1], qf[1][kk][2], qf[1][kk][3], r0, r2);
                MMA_F16(sacc[1][jp*2+1][0], sacc[1][jp*2+1][1], sacc[1][jp*2+1][2], sacc[1][jp*2+1][3],
                        qf[1][kk][0], qf[1][kk][1], qf[1][kk][2], qf[1][kk][3], r1, r3);
            }
        }

        // ---- online softmax (max only; sums come free from ones-column) ----
        unsigned ph2[2][8][2];
        #pragma unroll
        for (int mt = 0; mt < 2; mt++) {
            float mx0 = -1e30f, mx1 = -1e30f;
            #pragma unroll
            for (int j = 0; j < 8; j++) {
                mx0 = fmaxf(mx0, fmaxf(sacc[mt][j][0], sacc[mt][j][1]));
                mx1 = fmaxf(mx1, fmaxf(sacc[mt][j][2], sacc[mt][j][3]));
            }
            mx0 = fmaxf(mx0, __shfl_xor_sync(0xffffffffu, mx0, 1));
            mx0 = fmaxf(mx0, __shfl_xor_sync(0xffffffffu, mx0, 2));
            mx1 = fmaxf(mx1, __shfl_xor_sync(0xffffffffu, mx1, 1));
            mx1 = fmaxf(mx1, __shfl_xor_sync(0xffffffffu, mx1, 2));

            float mn0 = fmaxf(mrow[mt][0], mx0);
            float mn1 = fmaxf(mrow[mt][1], mx1);
            float corr0 = __expf(mrow[mt][0] - mn0);
            float corr1 = __expf(mrow[mt][1] - mn1);
            mrow[mt][0] = mn0; mrow[mt][1] = mn1;

            float me0 = mn0 * LOG2E, me1 = mn1 * LOG2E;
            #pragma unroll
            for (int j = 0; j < 8; j++) {
                float d0 = fmaf(sacc[mt][j][0], LOG2E, -me0);
                float d1 = fmaf(sacc[mt][j][1], LOG2E, -me0);
                float d2 = fmaf(sacc[mt][j][2], LOG2E, -me1);
                float d3 = fmaf(sacc[mt][j][3], LOG2E, -me1);
                unsigned u0 = packh2(d0, d1);
                unsigned u1 = packh2(d2, d3);
                asm("ex2.approx.f16x2 %0, %0;" : "+r"(u0));
                asm("ex2.approx.f16x2 %0, %0;" : "+r"(u1));
                ph2[mt][j][0] = u0;
                ph2[mt][j][1] = u1;
            }

            #pragma unroll
            for (int j = 0; j < 8; j++) {
                of[mt][j][0] *= corr0; of[mt][j][1] *= corr0;
                of[mt][j][2] *= corr1; of[mt][j][3] *= corr1;
            }
            ofl[mt][0] *= corr0; ofl[mt][1] *= corr0;
            ofl[mt][2] *= corr1; ofl[mt][3] *= corr1;
        }

        // ---- O += P V  (plus ones-column -> l) ----
        #pragma unroll
        for (int kk = 0; kk < 4; kk++) {
            #pragma unroll
            for (int jp = 0; jp < 4; jp++) {
                unsigned r0, r1, r2, r3;
                ldm_x4_t(r0, r1, r2, r3,
                         vbuf + ((kk * 16 + lr) * KVST + jp * 16 + lc) * 2);
                #pragma unroll
                for (int mt = 0; mt < 2; mt++) {
                    MMA_F16(of[mt][jp*2][0], of[mt][jp*2][1], of[mt][jp*2][2], of[mt][jp*2][3],
                            ph2[mt][kk*2][0], ph2[mt][kk*2][1],
                            ph2[mt][kk*2+1][0], ph2[mt][kk*2+1][1], r0, r1);
                    MMA_F16(of[mt][jp*2+1][0], of[mt][jp*2+1][1], of[mt][jp*2+1][2], of[mt][jp*2+1][3],
                            ph2[mt][kk*2][0], ph2[mt][kk*2][1],
                            ph2[mt][kk*2+1][0], ph2[mt][kk*2+1][1], r2, r3);
                }
            }
            // l chunk: V cols 64..71 (col 64 = 1), read as x4, use first matrix pair
            {
                unsigned r0, r1, r2, r3;
                ldm_x4_t(r0, r1, r2, r3,
                         vbuf + ((kk * 16 + lr) * KVST + 64 + lc) * 2);
                #pragma unroll
                for (int mt = 0; mt < 2; mt++)
                    MMA_F16(ofl[mt][0], ofl[mt][1], ofl[mt][2], ofl[mt][3],
                            ph2[mt][kk*2][0], ph2[mt][kk*2][1],
                            ph2[mt][kk*2+1][0], ph2[mt][kk*2+1][1], r0, r1);
            }
        }
        __syncthreads();
    }

    // ---- epilogue: l lives in col 64 -> lane t=0 (c0 row g, c2 row g+8) ----
    const int b = bh >> 4, h = bh & 15;
    const int srcl = lane & 28;
    #pragma unroll
    for (int mt = 0; mt < 2; mt++) {
        float l0 = __shfl_sync(0xffffffffu, ofl[mt][0], srcl);
        float l1 = __shfl_sync(0xffffffffu, ofl[mt][2], srcl);
        float inv0 = 1.0f / l0;
        float inv1 = 1.0f / l1;
        size_t row0 = ((size_t)b * N_ + qbase + mt * 16 + g) * D_ + h * HD_;
        size_t row1 = row0 + (size_t)8 * D_;
        #pragma unroll
        for (int j = 0; j < 8; j++) {
            int d = j * 8 + t * 2;
            *(__half2*)&g_oh[row0 + d] = __floats2half2_rn(of[mt][j][0] * inv0, of[mt][j][1] * inv0);
            *(__half2*)&g_oh[row1 + d] = __floats2half2_rn(of[mt][j][2] * inv1, of[mt][j][3] * inv1);
        }
    }
}

// ---------------- launch ---------------------------------------------------------
extern "C" void kernel_launch(void* const* d_in, const int* in_sizes, int n_in,
                              void* d_out, int out_size)
{
    const float* x       = (const float*)d_in[0];
    const float* Wqkv    = (const float*)d_in[1];
    const float* bqkv    = (const float*)d_in[2];
    const float* Wout    = (const float*)d_in[3];
    const float* bout    = (const float*)d_in[4];
    const float* q_scale = (const float*)d_in[5];
    const float* k_scale = (const float*)d_in[6];
    float* out = (float*)d_out;

    __half *xh_p, *wqkvh_p, *wouth_p, *oh_p;
    cudaGetSymbolAddress((void**)&xh_p,    g_xh);
    cudaGetSymbolAddress((void**)&wqkvh_p, g_wqkvh);
    cudaGetSymbolAddress((void**)&wouth_p, g_wouth);
    cudaGetSymbolAddress((void**)&oh_p,    g_oh);

    cudaFuncSetAttribute(gemm_f16_core<0>,
                         cudaFuncAttributeMaxDynamicSharedMemorySize, GEMM_SMEM_BYTES);
    cudaFuncSetAttribute(gemm_f16_core<1>,
                         cudaFuncAttributeMaxDynamicSharedMemorySize, GEMM_SMEM_BYTES);
    cudaFuncSetAttribute(attn_f16_kernel,
                         cudaFuncAttributeMaxDynamicSharedMemorySize, ATTN_SMEM_BYTES);

    // 0. fused conversions + RoPE tables
    int conv_n = X4_ + W14_ + W24_;
    f2h_all_kernel<<<(conv_n + 255) / 256, 256>>>(x, Wqkv, Wout);
    rope_tables_kernel<<<(N_ * 32 + 255) / 256, 256>>>();

    // 1. QKV GEMM with fused bias+RMSNorm+RoPE+reshape
    dim3 g1(N3_ / GBN, M_ / GBM);
    gemm_f16_core<1><<<g1, 256, GEMM_SMEM_BYTES>>>(
        xh_p, wqkvh_p, bqkv, nullptr, q_scale, k_scale, M_, N3_, D_);

    // 2. Flash attention
    attn_f16_kernel<<<dim3(N_ / 128, B_ * H_), 128, ATTN_SMEM_BYTES>>>();

    // 3. Output GEMM
    dim3 g2(D_ / GBN, M_ / GBM);
    gemm_f16_core<0><<<g2, 256, GEMM_SMEM_BYTES>>>(
        oh_p, wouth_p, bout, out, nullptr, nullptr, M_, D_, D_);
}

// round 10
// speedup vs baseline: 7.9779x; 1.1160x over previous
#include <cuda_runtime.h>
#include <cuda_fp16.h>
#include <math.h>

#define B_  8
#define N_  1024
#define D_  1024
#define H_  16
#define HD_ 64
#define M_  (B_ * N_)
#define N3_ (3 * D_)

// ---------------- scratch ----------------------------------------------------
__device__ __half g_xh [(size_t)M_ * D_];
__device__ __half g_wqkvh[(size_t)D_ * N3_];
__device__ __half g_wouth[(size_t)D_ * D_];
__device__ __half g_qh [(size_t)B_ * H_ * N_ * HD_];
__device__ __half g_kh [(size_t)B_ * H_ * N_ * HD_];
__device__ __half g_vh [(size_t)B_ * H_ * N_ * HD_];
__device__ __half g_oh [(size_t)M_ * D_];
__device__ float  g_cos[N_ * 32];
__device__ float  g_sin[N_ * 32];

// ---------------- helpers -----------------------------------------------------
#define MMA_F16(d0,d1,d2,d3,a0,a1,a2,a3,b0,b1)                            \
    asm volatile(                                                          \
        "mma.sync.aligned.m16n8k16.row.col.f32.f16.f16.f32 "               \
        "{%0,%1,%2,%3},{%4,%5,%6,%7},{%8,%9},{%0,%1,%2,%3};\n"             \
        : "+f"(d0), "+f"(d1), "+f"(d2), "+f"(d3)                           \
        : "r"(a0), "r"(a1), "r"(a2), "r"(a3), "r"(b0), "r"(b1))

__device__ __forceinline__ void ldm_x4(unsigned& r0, unsigned& r1,
                                       unsigned& r2, unsigned& r3, unsigned a) {
    asm volatile("ldmatrix.sync.aligned.m8n8.x4.shared.b16 {%0,%1,%2,%3}, [%4];\n"
                 : "=r"(r0), "=r"(r1), "=r"(r2), "=r"(r3) : "r"(a));
}
__device__ __forceinline__ void ldm_x4_t(unsigned& r0, unsigned& r1,
                                         unsigned& r2, unsigned& r3, unsigned a) {
    asm volatile("ldmatrix.sync.aligned.m8n8.x4.trans.shared.b16 {%0,%1,%2,%3}, [%4];\n"
                 : "=r"(r0), "=r"(r1), "=r"(r2), "=r"(r3) : "r"(a));
}
__device__ __forceinline__ void cp16(unsigned smem_addr, const void* gptr) {
    asm volatile("cp.async.cg.shared.global [%0], [%1], 16;\n"
                 :: "r"(smem_addr), "l"(gptr));
}
#define CP_COMMIT() asm volatile("cp.async.commit_group;\n")
#define CP_WAIT(n)  asm volatile("cp.async.wait_group %0;\n" :: "n"(n))

__device__ __forceinline__ unsigned packh2(float a, float b) {
    __half2 h = __floats2half2_rn(a, b);
    return *(unsigned*)&h;
}

// ---------------- fused fp32 -> fp16 conversion --------------------------------
#define X4_  (M_ * D_ / 4)
#define W14_ (D_ * N3_ / 4)
#define W24_ (D_ * D_ / 4)
__global__ void f2h_all_kernel(const float* __restrict__ x,
                               const float* __restrict__ w1,
                               const float* __restrict__ w2) {
    int i = blockIdx.x * blockDim.x + threadIdx.x;
    const float* src;
    __half* dst;
    int off;
    if (i < X4_) {
        src = x;  dst = g_xh;    off = i;
    } else if (i < X4_ + W14_) {
        src = w1; dst = g_wqkvh; off = i - X4_;
    } else if (i < X4_ + W14_ + W24_) {
        src = w2; dst = g_wouth; off = i - X4_ - W14_;
    } else return;
    float4 v = ((const float4*)src)[off];
    ((__half2*)dst)[off * 2]     = __floats2half2_rn(v.x, v.y);
    ((__half2*)dst)[off * 2 + 1] = __floats2half2_rn(v.z, v.w);
}

// ---------------- RoPE tables ---------------------------------------------------
__global__ void rope_tables_kernel() {
    int i = blockIdx.x * blockDim.x + threadIdx.x;
    if (i >= N_ * 32) return;
    int n = i >> 5, j = i & 31;
    int pos = (j < 16) ? (n >> 5) : (n & 31);
    int jj  = (j < 16) ? j : (j - 16);
    float invf = exp2f(-(float)jj * (13.287712379549449f / 16.0f));
    float ang  = (float)pos * invf;
    g_cos[i] = cosf(ang);
    g_sin[i] = sinf(ang);
}

// ====================== fp16 tensor-core GEMM + epilogues ======================
// 4-stage cp.async pipeline, single barrier per k-tile, true depth-2 prefetch.
#define GBM 128
#define GBN 256
#define GBK 32
#define AST 40
#define BST 264
#define A_HALF (GBM * AST)
#define B_HALF (GBK * BST)
#define STG_HALF (A_HALF + B_HALF)
#define NSTAGE 4
#define GEMM_SMEM_BYTES (NSTAGE * STG_HALF * 2)   // 108544

template<int FUSED>
__global__ __launch_bounds__(256, 1)
void gemm_f16_core(const __half* __restrict__ A, const __half* __restrict__ Bm,
                   const float* __restrict__ bias, float* __restrict__ C,
                   const float* __restrict__ q_scale,
                   const float* __restrict__ k_scale,
                   int M, int N, int K)
{
    extern __shared__ __half sm[];
    const unsigned smem_base = (unsigned)__cvta_generic_to_shared(sm);

    const int tid  = threadIdx.x;
    const int warp = tid >> 5;
    const int lane = tid & 31;
    const int wm   = warp & 1;
    const int wn   = warp >> 1;
    const int g    = lane >> 2;
    const int t    = lane & 3;
    const int brow = blockIdx.y * GBM;
    const int bcol = blockIdx.x * GBN;

    float acc[4][8][4];
    #pragma unroll
    for (int i = 0; i < 4; i++)
        #pragma unroll
        for (int j = 0; j < 8; j++)
            #pragma unroll
            for (int c = 0; c < 4; c++) acc[i][j][c] = 0.f;

    const int T = K / GBK;

    auto issue = [&](int s, int k0) {
        unsigned abase = smem_base + (s * STG_HALF) * 2;
        unsigned bbase = abase + A_HALF * 2;
        #pragma unroll
        for (int it = 0; it < 2; it++) {
            int idx = tid + it * 256;
            int row = idx >> 2, cc = (idx & 3) * 8;
            cp16(abase + (row * AST + cc) * 2,
                 &A[(size_t)(brow + row) * K + k0 + cc]);
        }
        #pragma unroll
        for (int it = 0; it < 4; it++) {
            int idx = tid + it * 256;
            int row = idx >> 5, cc = (idx & 31) * 8;
            cp16(bbase + (row * BST + cc) * 2,
                 &Bm[(size_t)(k0 + row) * N + bcol + cc]);
        }
    };

    issue(0, 0);       CP_COMMIT();
    issue(1, GBK);     CP_COMMIT();
    issue(2, 2 * GBK); CP_COMMIT();

    const int a_r = (lane & 15);
    const int a_c = (lane >> 4) * 8;
    for (int ti = 0; ti < T; ti++) {
        CP_WAIT(2);
        __syncthreads();

        unsigned abase = smem_base + ((ti & 3) * STG_HALF) * 2;
        unsigned bbase = abase + A_HALF * 2;

        #pragma unroll
        for (int ks = 0; ks < 2; ks++) {
            const int kb = ks * 16;
            unsigned af[4][4], bf[8][2];
            #pragma unroll
            for (int i = 0; i < 4; i++) {
                int m0 = wm * 64 + i * 16;
                ldm_x4(af[i][0], af[i][1], af[i][2], af[i][3],
                       abase + ((m0 + a_r) * AST + kb + a_c) * 2);
            }
            #pragma unroll
            for (int jp = 0; jp < 4; jp++) {
                int n0 = wn * 64 + jp * 16;
                unsigned r0, r1, r2, r3;
                ldm_x4_t(r0, r1, r2, r3,
                         bbase + ((kb + a_r) * BST + n0 + a_c) * 2);
                bf[jp * 2][0]     = r0; bf[jp * 2][1]     = r1;
                bf[jp * 2 + 1][0] = r2; bf[jp * 2 + 1][1] = r3;
            }
            #pragma unroll
            for (int i = 0; i < 4; i++)
                #pragma unroll
                for (int j = 0; j < 8; j++)
                    MMA_F16(acc[i][j][0], acc[i][j][1], acc[i][j][2], acc[i][j][3],
                            af[i][0], af[i][1], af[i][2], af[i][3],
                            bf[j][0], bf[j][1]);
        }

        if (ti + 3 < T) issue((ti + 3) & 3, (ti + 3) * GBK);
        CP_COMMIT();
    }

    float bb[16];
    #pragma unroll
    for (int j = 0; j < 8; j++) {
        bb[j * 2]     = bias[bcol + wn * 64 + j * 8 + t * 2];
        bb[j * 2 + 1] = bias[bcol + wn * 64 + j * 8 + t * 2 + 1];
    }
    #pragma unroll
    for (int i = 0; i < 4; i++)
        #pragma unroll
        for (int j = 0; j < 8; j++) {
            acc[i][j][0] += bb[j * 2]; acc[i][j][1] += bb[j * 2 + 1];
            acc[i][j][2] += bb[j * 2]; acc[i][j][3] += bb[j * 2 + 1];
        }

    if (FUSED == 0) {
        #pragma unroll
        for (int i = 0; i < 4; i++) {
            int row = brow + wm * 64 + i * 16 + g;
            #pragma unroll
            for (int j = 0; j < 8; j++) {
                int col = bcol + wn * 64 + j * 8 + t * 2;
                float2 v0 = { acc[i][j][0], acc[i][j][1] };
                float2 v1 = { acc[i][j][2], acc[i][j][3] };
                *(float2*)&C[(size_t)row * N + col]       = v0;
                *(float2*)&C[(size_t)(row + 8) * N + col] = v1;
            }
        }
        return;
    }

    const int region = blockIdx.x >> 2;
    const int h      = (blockIdx.x & 3) * 4 + wn;

    if (region == 2) {
        #pragma unroll
        for (int i = 0; i < 4; i++) {
            int grow = brow + wm * 64 + i * 16 + g;
            int nn = grow & (N_ - 1), bb_ = grow >> 10;
            size_t dst0 = ((size_t)(bb_ * H_ + h) * N_ + nn) * HD_;
            size_t dst1 = dst0 + 8 * HD_;
            #pragma unroll
            for (int j = 0; j < 8; j++) {
                int d = j * 8 + t * 2;
                *(__half2*)&g_vh[dst0 + d] = __floats2half2_rn(acc[i][j][0], acc[i][j][1]);
                *(__half2*)&g_vh[dst1 + d] = __floats2half2_rn(acc[i][j][2], acc[i][j][3]);
            }
        }
    } else {
        const float* scv = (region == 0) ? q_scale : k_scale;
        __half* outp     = (region == 0) ? g_qh : g_kh;
        const float rsmul = (region == 0) ? 0.125f : 1.0f;
        float scr[16];
        #pragma unroll
        for (int j = 0; j < 8; j++) {
            scr[j * 2]     = scv[j * 8 + t * 2];
            scr[j * 2 + 1] = scv[j * 8 + t * 2 + 1];
        }
        #pragma unroll
        for (int i = 0; i < 4; i++) {
            float ss0 = 0.f, ss1 = 0.f;
            #pragma unroll
            for (int j = 0; j < 8; j++) {
                ss0 += acc[i][j][0] * acc[i][j][0] + acc[i][j][1] * acc[i][j][1];
                ss1 += acc[i][j][2] * acc[i][j][2] + acc[i][j][3] * acc[i][j][3];
            }
            ss0 += __shfl_xor_sync(0xffffffffu, ss0, 1);
            ss0 += __shfl_xor_sync(0xffffffffu, ss0, 2);
            ss1 += __shfl_xor_sync(0xffffffffu, ss1, 1);
            ss1 += __shfl_xor_sync(0xffffffffu, ss1, 2);
            float rs0 = rsqrtf(ss0 * (1.0f / HD_) + 1e-6f) * rsmul;
            float rs1 = rsqrtf(ss1 * (1.0f / HD_) + 1e-6f) * rsmul;

            int grow = brow + wm * 64 + i * 16 + g;
            int nn = grow & (N_ - 1), bb_ = grow >> 10;
            size_t dst0 = ((size_t)(bb_ * H_ + h) * N_ + nn) * HD_;
            size_t dst1 = dst0 + 8 * HD_;
            #pragma unroll
            for (int j = 0; j < 4; j++) {
                int d = j * 8 + t * 2;
                float c00 = g_cos[nn * 32 + d],           s00 = g_sin[nn * 32 + d];
                float c01 = g_cos[nn * 32 + d + 1],       s01 = g_sin[nn * 32 + d + 1];
                float c10 = g_cos[(nn + 8) * 32 + d],     s10 = g_sin[(nn + 8) * 32 + d];
                float c11 = g_cos[(nn + 8) * 32 + d + 1], s11 = g_sin[(nn + 8) * 32 + d + 1];
                float a0 = acc[i][j][0] * rs0 * scr[j * 2];
                float a1 = acc[i][j][1] * rs0 * scr[j * 2 + 1];
                float p0 = acc[i][j + 4][0] * rs0 * scr[(j + 4) * 2];
                float p1 = acc[i][j + 4][1] * rs0 * scr[(j + 4) * 2 + 1];
                *(__half2*)&outp[dst0 + d]      = __floats2half2_rn(a0 * c00 - p0 * s00, a1 * c01 - p1 * s01);
                *(__half2*)&outp[dst0 + d + 32] = __floats2half2_rn(a0 * s00 + p0 * c00, a1 * s01 + p1 * c01);
                float e0 = acc[i][j][2] * rs1 * scr[j * 2];
                float e1 = acc[i][j][3] * rs1 * scr[j * 2 + 1];
                float q0 = acc[i][j + 4][2] * rs1 * scr[(j + 4) * 2];
                float q1 = acc[i][j + 4][3] * rs1 * scr[(j + 4) * 2 + 1];
                *(__half2*)&outp[dst1 + d]      = __floats2half2_rn(e0 * c10 - q0 * s10, e1 * c11 - q1 * s11);
                *(__half2*)&outp[dst1 + d + 32] = __floats2half2_rn(e0 * s10 + q0 * c10, e1 * s11 + q1 * c11);
            }
        }
    }
}

// ====== fp16 flash attention: online max + f16x2 exp + ones-column, 3-stage ====
#define KVST 88
#define KV_TILE_HALF (64 * KVST)
#define ATTN_SMEM_BYTES (6 * KV_TILE_HALF * 2)   // 67584

__global__ __launch_bounds__(128)
void attn_f16_kernel()
{
    extern __shared__ __half asm_[];
    const unsigned smem_base = (unsigned)__cvta_generic_to_shared(asm_);

    const int tid  = threadIdx.x;
    const int warp = tid >> 5;
    const int lane = tid & 31;
    const int g    = lane >> 2;
    const int t    = lane & 3;
    const int bh   = blockIdx.y;
    const int qbase = blockIdx.x * 128 + warp * 32;
    const size_t base = (size_t)bh * N_ * HD_;
    const float LOG2E = 1.44269504f;

    // init V pad columns 64..71 for all 3 V bufs (col 64 = 1.0 -> row-sum l)
    for (int i = tid; i < 3 * 64; i += 128) {
        int buf = i >> 6, row = i & 63;
        __half* p = asm_ + (size_t)(3 + buf) * KV_TILE_HALF + row * KVST + 64;
        p[0] = __float2half(1.0f);
        #pragma unroll
        for (int j = 1; j < 8; j++) p[j] = __float2half(0.0f);
    }

    unsigned qf[2][4][4];
    #pragma unroll
    for (int mt = 0; mt < 2; mt++) {
        const __half* Q0 = g_qh + base + (size_t)(qbase + mt * 16 + g) * HD_;
        const __half* Q1 = Q0 + 8 * HD_;
        #pragma unroll
        for (int kk = 0; kk < 4; kk++) {
            qf[mt][kk][0] = *(const unsigned*)&Q0[kk * 16 + 2 * t];
            qf[mt][kk][1] = *(const unsigned*)&Q1[kk * 16 + 2 * t];
            qf[mt][kk][2] = *(const unsigned*)&Q0[kk * 16 + 8 + 2 * t];
            qf[mt][kk][3] = *(const unsigned*)&Q1[kk * 16 + 8 + 2 * t];
        }
    }

    float of[2][8][4];
    float ofl[2][4];
    #pragma unroll
    for (int mt = 0; mt < 2; mt++) {
        #pragma unroll
        for (int j = 0; j < 8; j++)
            #pragma unroll
            for (int c = 0; c < 4; c++) of[mt][j][c] = 0.f;
        #pragma unroll
        for (int c = 0; c < 4; c++) ofl[mt][c] = 0.f;
    }
    float mrow[2][2] = {{-1e30f, -1e30f}, {-1e30f, -1e30f}};

    auto issue_tile = [&](int buf, int tile) {
        unsigned kb = smem_base + buf * KV_TILE_HALF * 2;
        unsigned vb = smem_base + (3 + buf) * KV_TILE_HALF * 2;
        const __half* kg = g_kh + base + (size_t)tile * 64 * HD_;
        const __half* vg = g_vh + base + (size_t)tile * 64 * HD_;
        #pragma unroll
        for (int it = 0; it < 4; it++) {
            int idx = tid + it * 128;
            int row = idx >> 3, cc = (idx & 7) * 8;
            cp16(kb + (row * KVST + cc) * 2, kg + row * HD_ + cc);
            cp16(vb + (row * KVST + cc) * 2, vg + row * HD_ + cc);
        }
    };

    issue_tile(0, 0); CP_COMMIT();
    issue_tile(1, 1); CP_COMMIT();

    const int lr = lane & 15;
    const int lc = (lane >> 4) * 8;

    for (int tile = 0; tile < N_ / 64; tile++) {
        CP_WAIT(1);
        __syncthreads();

        int bufi = tile % 3;
        unsigned kbuf = smem_base + bufi * KV_TILE_HALF * 2;
        unsigned vbuf = smem_base + (3 + bufi) * KV_TILE_HALF * 2;

        // ---- S = Q K^T ----
        float sacc[2][8][4];
        #pragma unroll
        for (int mt = 0; mt < 2; mt++)
            #pragma unroll
            for (int j = 0; j < 8; j++)
                #pragma unroll
                for (int c = 0; c < 4; c++) sacc[mt][j][c] = 0.f;

        #pragma unroll
        for (int kk = 0; kk < 4; kk++) {
            #pragma unroll
            for (int jp = 0; jp < 4; jp++) {
                unsigned r0, r1, r2, r3;
                int krow = jp * 16 + ((lane >> 3) & 1) * 8 + (lane & 7);
                ldm_x4(r0, r1, r2, r3,
                       kbuf + (krow * KVST + kk * 16 + lc) * 2);
                MMA_F16(sacc[0][jp*2][0], sacc[0][jp*2][1], sacc[0][jp*2][2], sacc[0][jp*2][3],
                        qf[0][kk][0], qf[0][kk][1], qf[0][kk][2], qf[0][kk][3], r0, r2);
                MMA_F16(sacc[0][jp*2+1][0], sacc[0][jp*2+1][1], sacc[0][jp*2+1][2], sacc[0][jp*2+1][3],
                        qf[0][kk][0], qf[0][kk][1], qf[0][kk][2], qf[0][kk][3], r1, r3);
                MMA_F16(sacc[1][jp*2][0], sacc[1][jp*2][1], sacc[1][jp*2][2], sacc[1][jp*2][3],
                        qf[1][kk][0], qf[1][kk][1], qf[1][kk][2], qf[1][kk][3], r0, r2);
                MMA_F16(sacc[1][jp*2+1][0], sacc[1][jp*2+1][1], sacc[1][jp*2+1][2], sacc[1][jp*2+1][3],
                        qf[1][kk][0], qf[1][kk][1], qf[1][kk][2], qf[1][kk][3], r1, r3);
            }
        }

        // ---- online softmax (per-tile max; sums from ones-column) ----
        unsigned ph2[2][8][2];
        #pragma unroll
        for (int mt = 0; mt < 2; mt++) {
            float mx0 = -1e30f, mx1 = -1e30f;
            #pragma unroll
            for (int j = 0; j < 8; j++) {
                mx0 = fmaxf(mx0, fmaxf(sacc[mt][j][0], sacc[mt][j][1]));
                mx1 = fmaxf(mx1, fmaxf(sacc[mt][j][2], sacc[mt][j][3]));
            }
            mx0 = fmaxf(mx0, __shfl_xor_sync(0xffffffffu, mx0, 1));
            mx0 = fmaxf(mx0, __shfl_xor_sync(0xffffffffu, mx0, 2));
            mx1 = fmaxf(mx1, __shfl_xor_sync(0xffffffffu, mx1, 1));
            mx1 = fmaxf(mx1, __shfl_xor_sync(0xffffffffu, mx1, 2));

            float mn0 = fmaxf(mrow[mt][0], mx0);
            float mn1 = fmaxf(mrow[mt][1], mx1);
            float corr0 = __expf(mrow[mt][0] - mn0);
            float corr1 = __expf(mrow[mt][1] - mn1);
            mrow[mt][0] = mn0; mrow[mt][1] = mn1;

            float me0 = mn0 * LOG2E, me1 = mn1 * LOG2E;
            #pragma unroll
            for (int j = 0; j < 8; j++) {
                float d0 = fmaf(sacc[mt][j][0], LOG2E, -me0);
                float d1 = fmaf(sacc[mt][j][1], LOG2E, -me0);
                float d2 = fmaf(sacc[mt][j][2], LOG2E, -me1);
                float d3 = fmaf(sacc[mt][j][3], LOG2E, -me1);
                unsigned u0 = packh2(d0, d1);
                unsigned u1 = packh2(d2, d3);
                asm("ex2.approx.f16x2 %0, %0;" : "+r"(u0));
                asm("ex2.approx.f16x2 %0, %0;" : "+r"(u1));
                ph2[mt][j][0] = u0;
                ph2[mt][j][1] = u1;
            }

            #pragma unroll
            for (int j = 0; j < 8; j++) {
                of[mt][j][0] *= corr0; of[mt][j][1] *= corr0;
                of[mt][j][2] *= corr1; of[mt][j][3] *= corr1;
            }
            ofl[mt][0] *= corr0; ofl[mt][1] *= corr0;
            ofl[mt][2] *= corr1; ofl[mt][3] *= corr1;
        }

        // ---- O += P V (plus ones-column -> l) ----
        #pragma unroll
        for (int kk = 0; kk < 4; kk++) {
            #pragma unroll
            for (int jp = 0; jp < 4; jp++) {
                unsigned r0, r1, r2, r3;
                ldm_x4_t(r0, r1, r2, r3,
                         vbuf + ((kk * 16 + lr) * KVST + jp * 16 + lc) * 2);
                #pragma unroll
                for (int mt = 0; mt < 2; mt++) {
                    MMA_F16(of[mt][jp*2][0], of[mt][jp*2][1], of[mt][jp*2][2], of[mt][jp*2][3],
                            ph2[mt][kk*2][0], ph2[mt][kk*2][1],
                            ph2[mt][kk*2+1][0], ph2[mt][kk*2+1][1], r0, r1);
                    MMA_F16(of[mt][jp*2+1][0], of[mt][jp*2+1][1], of[mt][jp*2+1][2], of[mt][jp*2+1][3],
                            ph2[mt][kk*2][0], ph2[mt][kk*2][1],
                            ph2[mt][kk*2+1][0], ph2[mt][kk*2+1][1], r2, r3);
                }
            }
            {
                unsigned r0, r1, r2, r3;
                ldm_x4_t(r0, r1, r2, r3,
                         vbuf + ((kk * 16 + lr) * KVST + 64 + lc) * 2);
                #pragma unroll
                for (int mt = 0; mt < 2; mt++)
                    MMA_F16(ofl[mt][0], ofl[mt][1], ofl[mt][2], ofl[mt][3],
                            ph2[mt][kk*2][0], ph2[mt][kk*2][1],
                            ph2[mt][kk*2+1][0], ph2[mt][kk*2+1][1], r0, r1);
            }
        }

        if (tile + 2 < N_ / 64) issue_tile((tile + 2) % 3, tile + 2);
        CP_COMMIT();
    }

    // ---- epilogue ----
    const int b = bh >> 4, h = bh & 15;
    const int srcl = lane & 28;
    #pragma unroll
    for (int mt = 0; mt < 2; mt++) {
        float l0 = __shfl_sync(0xffffffffu, ofl[mt][0], srcl);
        float l1 = __shfl_sync(0xffffffffu, ofl[mt][2], srcl);
        float inv0 = 1.0f / l0;
        float inv1 = 1.0f / l1;
        size_t row0 = ((size_t)b * N_ + qbase + mt * 16 + g) * D_ + h * HD_;
        size_t row1 = row0 + (size_t)8 * D_;
        #pragma unroll
        for (int j = 0; j < 8; j++) {
            int d = j * 8 + t * 2;
            *(__half2*)&g_oh[row0 + d] = __floats2half2_rn(of[mt][j][0] * inv0, of[mt][j][1] * inv0);
            *(__half2*)&g_oh[row1 + d] = __floats2half2_rn(of[mt][j][2] * inv1, of[mt][j][3] * inv1);
        }
    }
}

// ---------------- launch ---------------------------------------------------------
extern "C" void kernel_launch(void* const* d_in, const int* in_sizes, int n_in,
                              void* d_out, int out_size)
{
    const float* x       = (const float*)d_in[0];
    const float* Wqkv    = (const float*)d_in[1];
    const float* bqkv    = (const float*)d_in[2];
    const float* Wout    = (const float*)d_in[3];
    const float* bout    = (const float*)d_in[4];
    const float* q_scale = (const float*)d_in[5];
    const float* k_scale = (const float*)d_in[6];
    float* out = (float*)d_out;

    __half *xh_p, *wqkvh_p, *wouth_p, *oh_p;
    cudaGetSymbolAddress((void**)&xh_p,    g_xh);
    cudaGetSymbolAddress((void**)&wqkvh_p, g_wqkvh);
    cudaGetSymbolAddress((void**)&wouth_p, g_wouth);
    cudaGetSymbolAddress((void**)&oh_p,    g_oh);

    cudaFuncSetAttribute(gemm_f16_core<0>,
                         cudaFuncAttributeMaxDynamicSharedMemorySize, GEMM_SMEM_BYTES);
    cudaFuncSetAttribute(gemm_f16_core<1>,
                         cudaFuncAttributeMaxDynamicSharedMemorySize, GEMM_SMEM_BYTES);
    cudaFuncSetAttribute(attn_f16_kernel,
                         cudaFuncAttributeMaxDynamicSharedMemorySize, ATTN_SMEM_BYTES);

    int conv_n = X4_ + W14_ + W24_;
    f2h_all_kernel<<<(conv_n + 255) / 256, 256>>>(x, Wqkv, Wout);
    rope_tables_kernel<<<(N_ * 32 + 255) / 256, 256>>>();

    dim3 g1(N3_ / GBN, M_ / GBM);
    gemm_f16_core<1><<<g1, 256, GEMM_SMEM_BYTES>>>(
        xh_p, wqkvh_p, bqkv, nullptr, q_scale, k_scale, M_, N3_, D_);

    attn_f16_kernel<<<dim3(N_ / 128, B_ * H_), 128, ATTN_SMEM_BYTES>>>();

    dim3 g2(D_ / GBN, M_ / GBM);
    gemm_f16_core<0><<<g2, 256, GEMM_SMEM_BYTES>>>(
        oh_p, wouth_p, bout, out, nullptr, nullptr, M_, D_, D_);
}